// round 9
// baseline (speedup 1.0000x reference)
#include <cuda_runtime.h>
#include <math.h>
#include <stdint.h>

#define BATCH 32
#define DIMD  512
#define MSZ   1024
#define NSZ   1024
#define SINK_ITERS 5
#define MSPLIT 32

// ---------------- device scratch (static: no allocations) ----------------
__device__ float    g_K [(size_t)BATCH * MSZ * NSZ];   // 134 MB fp32 kernel matrix
__device__ uint16_t g_Kh[(size_t)BATCH * MSZ * NSZ];   //  67 MB bf16 shadow (Sinkhorn reads)
__device__ float g_n1[BATCH * MSZ];
__device__ float g_n2[BATCH * NSZ];
__device__ float g_u[BATCH * MSZ];
__device__ float g_v[BATCH * NSZ];
__device__ float g_vpart[(size_t)MSPLIT * BATCH * NSZ];
__device__ float g_rowS[BATCH * MSZ];
__device__ float g_wref[BATCH * MSZ * 3];
__device__ float g_cov[BATCH * 9];
__device__ float g_ca[BATCH * 3];
__device__ float g_cb[BATCH * 3];

// ---------------- PTX helpers ----------------
__device__ __forceinline__ uint32_t f2tf(float x) {
    uint32_t r;
    asm("cvt.rna.tf32.f32 %0, %1;" : "=r"(r) : "f"(x));
    return r;
}
__device__ __forceinline__ uint32_t pack_bf16x2(float lo, float hi) {
    uint32_t r;
    asm("cvt.rn.bf16x2.f32 %0, %1, %2;" : "=r"(r) : "f"(hi), "f"(lo));
    return r;
}
__device__ __forceinline__ float bf_lo(uint32_t u) { return __uint_as_float(u << 16); }
__device__ __forceinline__ float bf_hi(uint32_t u) { return __uint_as_float(u & 0xFFFF0000u); }

__device__ __forceinline__ void mma_tf32(float* c, uint32_t a0, uint32_t a1,
                                         uint32_t a2, uint32_t a3,
                                         uint32_t b0, uint32_t b1) {
    asm volatile(
        "mma.sync.aligned.m16n8k8.row.col.f32.tf32.tf32.f32 "
        "{%0,%1,%2,%3},{%4,%5,%6,%7},{%8,%9},{%0,%1,%2,%3};"
        : "+f"(c[0]), "+f"(c[1]), "+f"(c[2]), "+f"(c[3])
        : "r"(a0), "r"(a1), "r"(a2), "r"(a3), "r"(b0), "r"(b1));
}

// ---------------- generic helpers ----------------
__device__ __forceinline__ float blockReduceB(float v, volatile float* sred) {
    int lane = threadIdx.x & 31;
    int wid = threadIdx.x >> 5;
    #pragma unroll
    for (int o = 16; o > 0; o >>= 1) v += __shfl_down_sync(0xffffffffu, v, o);
    if (lane == 0) sred[wid] = v;
    __syncthreads();
    if (threadIdx.x < 32) {
        int nw = (blockDim.x + 31) >> 5;
        float x = (threadIdx.x < nw) ? sred[threadIdx.x] : 0.0f;
        #pragma unroll
        for (int o = 16; o > 0; o >>= 1) x += __shfl_down_sync(0xffffffffu, x, o);
        if (threadIdx.x == 0) sred[0] = x;
    }
    __syncthreads();
    float r = sred[0];
    __syncthreads();
    return r;
}

// ---------------- norms over D for (b, m), layout (B, D, len) ----------------
__global__ void norms_kernel(const float* __restrict__ E, float* __restrict__ out) {
    int idx = blockIdx.x * blockDim.x + threadIdx.x;
    int b = idx >> 10;
    int m = idx & 1023;
    const float* p = E + (size_t)b * DIMD * MSZ + m;
    float s = 0.0f;
    #pragma unroll 8
    for (int d = 0; d < DIMD; d++) {
        float x = p[(size_t)d * MSZ];
        s += x * x;
    }
    out[idx] = sqrtf(s);
}

// ---------------- TF32 mma.sync GEMM + exp epilogue (unchanged) --------------
#define KC 16
#define SSTR 136
__global__ void __launch_bounds__(256, 2) gemm_mma_kernel(
        const float* __restrict__ Ae, const float* __restrict__ Be,
        const float* __restrict__ lptr) {
    __shared__ uint32_t sA[2][KC][SSTR];
    __shared__ uint32_t sB[2][KC][SSTR];

    int b = blockIdx.z;
    int m0 = blockIdx.y * 128;
    int n0 = blockIdx.x * 128;
    int tid = threadIdx.x;
    int wid = tid >> 5;
    int lane = tid & 31;
    int g = lane >> 2;
    int tig = lane & 3;
    int warp_m = (wid >> 2) * 64;
    int warp_n = (wid & 3) * 32;

    const float* Ab = Ae + (size_t)b * DIMD * MSZ;
    const float* Bb = Be + (size_t)b * DIMD * NSZ;

    int kr0 = tid >> 5;
    int c40 = tid & 31;
    int kr1 = (tid + 256) >> 5;
    int c41 = c40;

    float acc[4][4][4];
    #pragma unroll
    for (int mi = 0; mi < 4; mi++)
        #pragma unroll
        for (int ni = 0; ni < 4; ni++)
            #pragma unroll
            for (int q = 0; q < 4; q++) acc[mi][ni][q] = 0.0f;

    float4 ra0, ra1, rb0, rb1;

    ra0 = *(const float4*)&Ab[(size_t)kr0 * MSZ + m0 + c40 * 4];
    ra1 = *(const float4*)&Ab[(size_t)kr1 * MSZ + m0 + c41 * 4];
    rb0 = *(const float4*)&Bb[(size_t)kr0 * NSZ + n0 + c40 * 4];
    rb1 = *(const float4*)&Bb[(size_t)kr1 * NSZ + n0 + c41 * 4];
    {
        uint32_t* pa0 = &sA[0][kr0][c40 * 4];
        uint32_t* pa1 = &sA[0][kr1][c41 * 4];
        uint32_t* pb0 = &sB[0][kr0][c40 * 4];
        uint32_t* pb1 = &sB[0][kr1][c41 * 4];
        pa0[0] = f2tf(ra0.x); pa0[1] = f2tf(ra0.y); pa0[2] = f2tf(ra0.z); pa0[3] = f2tf(ra0.w);
        pa1[0] = f2tf(ra1.x); pa1[1] = f2tf(ra1.y); pa1[2] = f2tf(ra1.z); pa1[3] = f2tf(ra1.w);
        pb0[0] = f2tf(rb0.x); pb0[1] = f2tf(rb0.y); pb0[2] = f2tf(rb0.z); pb0[3] = f2tf(rb0.w);
        pb1[0] = f2tf(rb1.x); pb1[1] = f2tf(rb1.y); pb1[2] = f2tf(rb1.z); pb1[3] = f2tf(rb1.w);
    }
    __syncthreads();

    const int NCH = DIMD / KC;
    for (int c = 0; c < NCH; c++) {
        if (c + 1 < NCH) {
            int kb = (c + 1) * KC;
            ra0 = *(const float4*)&Ab[(size_t)(kb + kr0) * MSZ + m0 + c40 * 4];
            ra1 = *(const float4*)&Ab[(size_t)(kb + kr1) * MSZ + m0 + c41 * 4];
            rb0 = *(const float4*)&Bb[(size_t)(kb + kr0) * NSZ + n0 + c40 * 4];
            rb1 = *(const float4*)&Bb[(size_t)(kb + kr1) * NSZ + n0 + c41 * 4];
        }

        int cb = c & 1;
        #pragma unroll
        for (int ks = 0; ks < 2; ks++) {
            int k0 = ks * 8;
            uint32_t bf[4][2];
            #pragma unroll
            for (int ni = 0; ni < 4; ni++) {
                int nn = warp_n + ni * 8 + g;
                bf[ni][0] = sB[cb][k0 + tig][nn];
                bf[ni][1] = sB[cb][k0 + tig + 4][nn];
            }
            #pragma unroll
            for (int mi = 0; mi < 4; mi++) {
                int mm = warp_m + mi * 16 + g;
                uint32_t a0 = sA[cb][k0 + tig][mm];
                uint32_t a1 = sA[cb][k0 + tig][mm + 8];
                uint32_t a2 = sA[cb][k0 + tig + 4][mm];
                uint32_t a3 = sA[cb][k0 + tig + 4][mm + 8];
                #pragma unroll
                for (int ni = 0; ni < 4; ni++)
                    mma_tf32(acc[mi][ni], a0, a1, a2, a3, bf[ni][0], bf[ni][1]);
            }
        }

        if (c + 1 < NCH) {
            int nb = (c + 1) & 1;
            uint32_t* pa0 = &sA[nb][kr0][c40 * 4];
            uint32_t* pa1 = &sA[nb][kr1][c41 * 4];
            uint32_t* pb0 = &sB[nb][kr0][c40 * 4];
            uint32_t* pb1 = &sB[nb][kr1][c41 * 4];
            pa0[0] = f2tf(ra0.x); pa0[1] = f2tf(ra0.y); pa0[2] = f2tf(ra0.z); pa0[3] = f2tf(ra0.w);
            pa1[0] = f2tf(ra1.x); pa1[1] = f2tf(ra1.y); pa1[2] = f2tf(ra1.z); pa1[3] = f2tf(ra1.w);
            pb0[0] = f2tf(rb0.x); pb0[1] = f2tf(rb0.y); pb0[2] = f2tf(rb0.z); pb0[3] = f2tf(rb0.w);
            pb1[0] = f2tf(rb1.x); pb1[1] = f2tf(rb1.y); pb1[2] = f2tf(rb1.z); pb1[3] = f2tf(rb1.w);
        }
        __syncthreads();
    }

    float linv = 1.0f / fmaxf(lptr[0], 1e-8f);
    float n2r[8];
    #pragma unroll
    for (int ni = 0; ni < 4; ni++) {
        int nc = n0 + warp_n + ni * 8 + 2 * tig;
        n2r[ni * 2]     = g_n2[b * NSZ + nc];
        n2r[ni * 2 + 1] = g_n2[b * NSZ + nc + 1];
    }
    #pragma unroll
    for (int mi = 0; mi < 4; mi++) {
        #pragma unroll
        for (int half = 0; half < 2; half++) {
            int m = m0 + warp_m + mi * 16 + g + half * 8;
            float n1v = g_n1[b * MSZ + m];
            size_t rowoff = ((size_t)(b * MSZ + m)) * NSZ + n0 + warp_n;
            float* Krow = g_K + rowoff;
            uint32_t* Khrow = (uint32_t*)(g_Kh + rowoff);
            #pragma unroll
            for (int ni = 0; ni < 4; ni++) {
                float x0 = acc[mi][ni][half * 2 + 0];
                float x1 = acc[mi][ni][half * 2 + 1];
                float d0 = fmaxf(n1v * n2r[ni * 2], 1e-6f);
                float d1 = fmaxf(n1v * n2r[ni * 2 + 1], 1e-6f);
                float o0 = expf(-(1.0f - x0 / d0) * linv);
                float o1 = expf(-(1.0f - x1 / d1) * linv);
                *(float2*)&Krow[ni * 8 + 2 * tig] = make_float2(o0, o1);
                Khrow[ni * 4 + tig] = pack_bf16x2(o0, o1);
            }
        }
    }
}

// ---------------- init u,v ----------------
__global__ void init_uv_kernel() {
    int idx = blockIdx.x * blockDim.x + threadIdx.x;
    if (idx < BATCH * MSZ) g_u[idx] = 1.0f / (float)MSZ;
    if (idx < BATCH * NSZ) g_v[idx] = 1.0f / (float)NSZ;
}

// ---------------- fused Sinkhorn: DRAM once, write-through SMEM --------------
// Phase A streams bf16 K rows (computing u) and write-throughs them to SMEM;
// Phase B computes column partials from SMEM. One DRAM pass per iteration.
#define SINK_SMEM_BYTES (64 * 1024 + 4096 + 128)
__global__ void __launch_bounds__(256) sink_fused_kernel(
        const float* __restrict__ lptr, const float* __restrict__ rptr) {
    extern __shared__ char smraw[];
    uint4* sK = (uint4*)smraw;                       // [32 rows][128 uint4] = 64 KB
    float* sv = (float*)(smraw + 64 * 1024);         // 1024 floats
    float* su = sv + 1024;                           // 32 floats

    int b = blockIdx.y;
    int m0 = blockIdx.x * 32;
    int tid = threadIdx.x;
    int wid = tid >> 5;
    int lane = tid & 31;

    // stage v (4 KB)
    ((float4*)sv)[tid] = *(const float4*)&g_v[b * NSZ + tid * 4];
    __syncthreads();

    float lv = lptr[0], rv = rptr[0];
    float fi = rv / fmaxf(rv + lv, 1e-8f);
    float a = 1.0f / (float)MSZ;
    const float4* sv4 = (const float4*)sv;

    // Phase A: warp w handles rows 4w..4w+3; write-through to SMEM
    #pragma unroll
    for (int rr = 0; rr < 4; rr++) {
        int r = (wid << 2) | rr;
        const uint4* Kr = (const uint4*)(g_Kh + ((size_t)(b * MSZ + m0 + r)) * NSZ);
        float s = 0.0f;
        #pragma unroll
        for (int j = 0; j < 4; j++) {
            int sl = j * 32 + lane;          // uint4 slot 0..127
            uint4 kk = Kr[sl];
            sK[r * 128 + sl] = kk;           // write-through (STS.128, conflict-free)
            float4 va = sv4[sl * 2];
            float4 vb = sv4[sl * 2 + 1];
            s += bf_lo(kk.x) * va.x + bf_hi(kk.x) * va.y
               + bf_lo(kk.y) * va.z + bf_hi(kk.y) * va.w
               + bf_lo(kk.z) * vb.x + bf_hi(kk.z) * vb.y
               + bf_lo(kk.w) * vb.z + bf_hi(kk.w) * vb.w;
        }
        #pragma unroll
        for (int o = 16; o > 0; o >>= 1) s += __shfl_down_sync(0xffffffffu, s, o);
        if (lane == 0) {
            float uu = powf(a / fmaxf(s, 1e-8f), fi);
            g_u[b * MSZ + m0 + r] = uu;
            su[r] = uu;
        }
    }
    __syncthreads();

    // Phase B: from SMEM. Thread owns 4 cols (uint2 = 4 bf16) over 32 rows.
    const uint16_t* sKh = (const uint16_t*)sK;
    float4 acc = make_float4(0.f, 0.f, 0.f, 0.f);
    #pragma unroll 8
    for (int r = 0; r < 32; r++) {
        float uu = su[r];
        uint2 kk = *(const uint2*)&sKh[r * 1024 + tid * 4];
        acc.x += uu * bf_lo(kk.x);
        acc.y += uu * bf_hi(kk.x);
        acc.z += uu * bf_lo(kk.y);
        acc.w += uu * bf_hi(kk.y);
    }
    *(float4*)&g_vpart[((size_t)blockIdx.x * BATCH + b) * NSZ + tid * 4] = acc;
}

// ---------------- v = (b / clip(colsum, eps))^fi ----------------
__global__ void sink_vpow_kernel(const float* __restrict__ lptr, const float* __restrict__ rptr) {
    int idx = blockIdx.x * blockDim.x + threadIdx.x;
    int b = idx >> 10;
    int n = idx & 1023;
    float s = 0.0f;
    #pragma unroll
    for (int z = 0; z < MSPLIT; z++)
        s += g_vpart[((size_t)z * BATCH + b) * NSZ + n];
    float lv = lptr[0], rv = rptr[0];
    float fi = rv / fmaxf(rv + lv, 1e-8f);
    float bb = 1.0f / (float)NSZ;
    g_v[idx] = powf(bb / fmaxf(s, 1e-8f), fi);
}

// ---------------- P = u*K*v, row sums, weighted_ref (fp32 K, one pass) -------
__global__ void compute_P_kernel(const float* __restrict__ tgt, float* __restrict__ Pout) {
    __shared__ float sred[32];
    int bm = blockIdx.x;
    int b = bm >> 10;
    float uu = g_u[bm];
    const float4* Krow = (const float4*)(g_K + (size_t)bm * NSZ);
    const float4* vrow = (const float4*)(g_v + b * NSZ);
    float4* Prow = (float4*)(Pout + (size_t)bm * NSZ);
    const float4* t0 = (const float4*)(tgt + ((size_t)b * 3 + 0) * NSZ);
    const float4* t1 = (const float4*)(tgt + ((size_t)b * 3 + 1) * NSZ);
    const float4* t2 = (const float4*)(tgt + ((size_t)b * 3 + 2) * NSZ);

    int t = threadIdx.x;
    float4 kk = Krow[t];
    float4 vv = vrow[t];
    float4 p;
    p.x = uu * kk.x * vv.x;
    p.y = uu * kk.y * vv.y;
    p.z = uu * kk.z * vv.z;
    p.w = uu * kk.w * vv.w;
    Prow[t] = p;

    float4 a0 = t0[t], a1 = t1[t], a2 = t2[t];
    float rs = p.x + p.y + p.z + p.w;
    float w0 = p.x * a0.x + p.y * a0.y + p.z * a0.z + p.w * a0.w;
    float w1 = p.x * a1.x + p.y * a1.y + p.z * a1.z + p.w * a1.w;
    float w2 = p.x * a2.x + p.y * a2.y + p.z * a2.z + p.w * a2.w;

    rs = blockReduceB(rs, sred);
    w0 = blockReduceB(w0, sred);
    w1 = blockReduceB(w1, sred);
    w2 = blockReduceB(w2, sred);
    if (threadIdx.x == 0) {
        g_rowS[bm] = rs;
        float inv = 1.0f / (rs + 1e-6f);
        g_wref[bm * 3 + 0] = w0 * inv;
        g_wref[bm * 3 + 1] = w1 * inv;
        g_wref[bm * 3 + 2] = w2 * inv;
    }
}

// ---------------- per-batch centroids + covariance ----------------
__global__ void cov_kernel(const float* __restrict__ src) {
    __shared__ float sred[32];
    int b = blockIdx.x;
    int t = threadIdx.x;

    float s = 0.0f;
    for (int m = t; m < MSZ; m += 256) s += g_rowS[b * MSZ + m];
    float S = blockReduceB(s, sred);
    float inv = 1.0f / (S + 1e-6f);

    float ca[3] = {0, 0, 0}, cb[3] = {0, 0, 0};
    for (int m = t; m < MSZ; m += 256) {
        float w = g_rowS[b * MSZ + m] * inv;
        #pragma unroll
        for (int d = 0; d < 3; d++) {
            ca[d] += w * src[((size_t)b * 3 + d) * MSZ + m];
            cb[d] += w * g_wref[(b * MSZ + m) * 3 + d];
        }
    }
    float CA[3], CB[3];
    #pragma unroll
    for (int d = 0; d < 3; d++) CA[d] = blockReduceB(ca[d], sred);
    #pragma unroll
    for (int d = 0; d < 3; d++) CB[d] = blockReduceB(cb[d], sred);

    float cv[9] = {0, 0, 0, 0, 0, 0, 0, 0, 0};
    for (int m = t; m < MSZ; m += 256) {
        float w = g_rowS[b * MSZ + m] * inv;
        float ac[3], bc[3];
        #pragma unroll
        for (int d = 0; d < 3; d++) {
            ac[d] = src[((size_t)b * 3 + d) * MSZ + m] - CA[d];
            bc[d] = g_wref[(b * MSZ + m) * 3 + d] - CB[d];
        }
        #pragma unroll
        for (int i = 0; i < 3; i++)
            #pragma unroll
            for (int j = 0; j < 3; j++)
                cv[i * 3 + j] += ac[i] * bc[j] * w;
    }
    #pragma unroll
    for (int k = 0; k < 9; k++) {
        float r = blockReduceB(cv[k], sred);
        if (t == 0) g_cov[b * 9 + k] = r;
    }
    if (t == 0) {
        #pragma unroll
        for (int d = 0; d < 3; d++) { g_ca[b * 3 + d] = CA[d]; g_cb[b * 3 + d] = CB[d]; }
    }
}

// ---------------- 3x3 SVD (fp64 Jacobi) + Kabsch R,t ----------------
__global__ void svd_kernel(float* __restrict__ out) {
    int b = threadIdx.x;
    if (b >= BATCH) return;

    double A[3][3];
    #pragma unroll
    for (int i = 0; i < 3; i++)
        #pragma unroll
        for (int j = 0; j < 3; j++)
            A[i][j] = (double)g_cov[b * 9 + i * 3 + j];

    double S[3][3];
    #pragma unroll
    for (int i = 0; i < 3; i++)
        #pragma unroll
        for (int j = 0; j < 3; j++) {
            double acc = 0.0;
            #pragma unroll
            for (int k = 0; k < 3; k++) acc += A[k][i] * A[k][j];
            S[i][j] = acc;
        }

    double V[3][3] = {{1, 0, 0}, {0, 1, 0}, {0, 0, 1}};
    const int PP[3] = {0, 0, 1};
    const int QQ[3] = {1, 2, 2};
    for (int sweep = 0; sweep < 20; sweep++) {
        for (int r = 0; r < 3; r++) {
            int p = PP[r], q = QQ[r];
            double apq = S[p][q];
            if (apq == 0.0) continue;
            double theta = (S[q][q] - S[p][p]) / (2.0 * apq);
            double tt = copysign(1.0, theta) / (fabs(theta) + sqrt(1.0 + theta * theta));
            double c = 1.0 / sqrt(1.0 + tt * tt);
            double sn = tt * c;
            for (int k = 0; k < 3; k++) {
                double skp = S[k][p], skq = S[k][q];
                S[k][p] = c * skp - sn * skq;
                S[k][q] = sn * skp + c * skq;
            }
            for (int k = 0; k < 3; k++) {
                double spk = S[p][k], sqk = S[q][k];
                S[p][k] = c * spk - sn * sqk;
                S[q][k] = sn * spk + c * sqk;
            }
            for (int k = 0; k < 3; k++) {
                double vkp = V[k][p], vkq = V[k][q];
                V[k][p] = c * vkp - sn * vkq;
                V[k][q] = sn * vkp + c * vkq;
            }
        }
    }

    double ev[3] = {S[0][0], S[1][1], S[2][2]};
    int idx[3] = {0, 1, 2};
    for (int i = 0; i < 2; i++)
        for (int j = i + 1; j < 3; j++)
            if (ev[idx[j]] > ev[idx[i]]) { int tmp = idx[i]; idx[i] = idx[j]; idx[j] = tmp; }

    double Vs[3][3];
    #pragma unroll
    for (int k = 0; k < 3; k++)
        for (int i = 0; i < 3; i++)
            Vs[k][i] = V[k][idx[i]];

    double U[3][3];
    double nrm[3];
    for (int i = 0; i < 3; i++) {
        double u0 = A[0][0] * Vs[0][i] + A[0][1] * Vs[1][i] + A[0][2] * Vs[2][i];
        double u1 = A[1][0] * Vs[0][i] + A[1][1] * Vs[1][i] + A[1][2] * Vs[2][i];
        double u2 = A[2][0] * Vs[0][i] + A[2][1] * Vs[1][i] + A[2][2] * Vs[2][i];
        double nm = sqrt(u0 * u0 + u1 * u1 + u2 * u2);
        nrm[i] = nm;
        double in = (nm > 1e-300) ? 1.0 / nm : 0.0;
        U[0][i] = u0 * in; U[1][i] = u1 * in; U[2][i] = u2 * in;
    }
    if (nrm[2] < 1e-12 * fmax(nrm[0], 1e-300)) {
        U[0][2] = U[1][0] * U[2][1] - U[2][0] * U[1][1];
        U[1][2] = U[2][0] * U[0][1] - U[0][0] * U[2][1];
        U[2][2] = U[0][0] * U[1][1] - U[1][0] * U[0][1];
    }

    double R[3][3];
    for (int i = 0; i < 3; i++)
        for (int j = 0; j < 3; j++)
            R[i][j] = Vs[i][0] * U[j][0] + Vs[i][1] * U[j][1] + Vs[i][2] * U[j][2];

    double det = R[0][0] * (R[1][1] * R[2][2] - R[1][2] * R[2][1])
               - R[0][1] * (R[1][0] * R[2][2] - R[1][2] * R[2][0])
               + R[0][2] * (R[1][0] * R[2][1] - R[1][1] * R[2][0]);
    if (!(det > 0.0)) {
        for (int i = 0; i < 3; i++)
            for (int j = 0; j < 3; j++)
                R[i][j] -= 2.0 * Vs[i][2] * U[j][2];
    }

    double ca[3] = {(double)g_ca[b * 3], (double)g_ca[b * 3 + 1], (double)g_ca[b * 3 + 2]};
    double cb[3] = {(double)g_cb[b * 3], (double)g_cb[b * 3 + 1], (double)g_cb[b * 3 + 2]};
    double tv[3];
    for (int i = 0; i < 3; i++)
        tv[i] = -(R[i][0] * ca[0] + R[i][1] * ca[1] + R[i][2] * ca[2]) + cb[i];

    for (int i = 0; i < 3; i++)
        for (int j = 0; j < 3; j++)
            out[b * 9 + i * 3 + j] = (float)R[i][j];
    for (int i = 0; i < 3; i++)
        out[288 + b * 3 + i] = (float)tv[i];
}

// ---------------- launch ----------------
extern "C" void kernel_launch(void* const* d_in, const int* in_sizes, int n_in,
                              void* d_out, int out_size) {
    const float* src_emb = (const float*)d_in[0];
    const float* tgt_emb = (const float*)d_in[1];
    const float* src     = (const float*)d_in[2];
    const float* tgt     = (const float*)d_in[3];
    const float* lptr    = (const float*)d_in[4];
    const float* rptr    = (const float*)d_in[5];
    float* out = (float*)d_out;
    float* Pout = out + BATCH * 9 + BATCH * 3;

    float* dn1; cudaGetSymbolAddress((void**)&dn1, g_n1);
    float* dn2; cudaGetSymbolAddress((void**)&dn2, g_n2);

    cudaFuncSetAttribute(sink_fused_kernel,
                         cudaFuncAttributeMaxDynamicSharedMemorySize, SINK_SMEM_BYTES);

    // launch order keeps gemm_mma_kernel as the 4th launch (ncu sample slot)
    init_uv_kernel<<<(BATCH * MSZ) / 256, 256>>>();
    norms_kernel<<<(BATCH * MSZ) / 256, 256>>>(src_emb, dn1);
    norms_kernel<<<(BATCH * NSZ) / 256, 256>>>(tgt_emb, dn2);

    dim3 ggrid(NSZ / 128, MSZ / 128, BATCH);
    gemm_mma_kernel<<<ggrid, 256>>>(src_emb, tgt_emb, lptr);

    for (int it = 0; it < SINK_ITERS; it++) {
        dim3 sgrid(MSZ / 32, BATCH);
        sink_fused_kernel<<<sgrid, 256, SINK_SMEM_BYTES>>>(lptr, rptr);
        sink_vpow_kernel<<<(BATCH * NSZ) / 256, 256>>>(lptr, rptr);
    }

    compute_P_kernel<<<BATCH * MSZ, 256>>>(tgt, Pout);
    cov_kernel<<<BATCH, 256>>>(src);
    svd_kernel<<<1, 32>>>(out);
}

// round 11
// speedup vs baseline: 1.0923x; 1.0923x over previous
#include <cuda_runtime.h>
#include <math.h>
#include <stdint.h>

#define BATCH 32
#define DIMD  512
#define MSZ   1024
#define NSZ   1024
#define SINK_ITERS 5
#define MSPLIT 32

// ---------------- device scratch (static: no allocations) ----------------
__device__ float    g_K [(size_t)BATCH * MSZ * NSZ];   // 134 MB fp32 kernel matrix
__device__ uint16_t g_Kh[(size_t)BATCH * MSZ * NSZ];   //  67 MB bf16 shadow (Sinkhorn reads)
__device__ float g_n1[BATCH * MSZ];
__device__ float g_n2[BATCH * NSZ];
__device__ float g_u[BATCH * MSZ];
__device__ float g_v[BATCH * NSZ];
__device__ float g_vpart[(size_t)MSPLIT * BATCH * NSZ];
__device__ float g_rowS[BATCH * MSZ];
__device__ float g_wref[BATCH * MSZ * 3];
__device__ float g_cov[BATCH * 9];
__device__ float g_ca[BATCH * 3];
__device__ float g_cb[BATCH * 3];

// ---------------- PTX helpers ----------------
__device__ __forceinline__ uint32_t f2tf(float x) {
    uint32_t r;
    asm("cvt.rna.tf32.f32 %0, %1;" : "=r"(r) : "f"(x));
    return r;
}
__device__ __forceinline__ uint32_t pack_bf16x2(float lo, float hi) {
    uint32_t r;
    asm("cvt.rn.bf16x2.f32 %0, %1, %2;" : "=r"(r) : "f"(hi), "f"(lo));
    return r;
}
__device__ __forceinline__ float bf_lo(uint32_t u) { return __uint_as_float(u << 16); }
__device__ __forceinline__ float bf_hi(uint32_t u) { return __uint_as_float(u & 0xFFFF0000u); }

__device__ __forceinline__ void mma_tf32(float* c, uint32_t a0, uint32_t a1,
                                         uint32_t a2, uint32_t a3,
                                         uint32_t b0, uint32_t b1) {
    asm volatile(
        "mma.sync.aligned.m16n8k8.row.col.f32.tf32.tf32.f32 "
        "{%0,%1,%2,%3},{%4,%5,%6,%7},{%8,%9},{%0,%1,%2,%3};"
        : "+f"(c[0]), "+f"(c[1]), "+f"(c[2]), "+f"(c[3])
        : "r"(a0), "r"(a1), "r"(a2), "r"(a3), "r"(b0), "r"(b1));
}

// ---------------- generic helpers ----------------
__device__ __forceinline__ float blockReduceB(float v, volatile float* sred) {
    int lane = threadIdx.x & 31;
    int wid = threadIdx.x >> 5;
    #pragma unroll
    for (int o = 16; o > 0; o >>= 1) v += __shfl_down_sync(0xffffffffu, v, o);
    if (lane == 0) sred[wid] = v;
    __syncthreads();
    if (threadIdx.x < 32) {
        int nw = (blockDim.x + 31) >> 5;
        float x = (threadIdx.x < nw) ? sred[threadIdx.x] : 0.0f;
        #pragma unroll
        for (int o = 16; o > 0; o >>= 1) x += __shfl_down_sync(0xffffffffu, x, o);
        if (threadIdx.x == 0) sred[0] = x;
    }
    __syncthreads();
    float r = sred[0];
    __syncthreads();
    return r;
}

// ---------------- fused norms: grid.y selects src/tgt embedding --------------
__global__ void norms2_kernel(const float* __restrict__ E1, const float* __restrict__ E2) {
    int idx = blockIdx.x * blockDim.x + threadIdx.x;
    const float* E = blockIdx.y ? E2 : E1;
    float* out = blockIdx.y ? g_n2 : g_n1;
    int b = idx >> 10;
    int m = idx & 1023;
    const float* p = E + (size_t)b * DIMD * MSZ + m;
    float s = 0.0f;
    #pragma unroll 8
    for (int d = 0; d < DIMD; d++) {
        float x = p[(size_t)d * MSZ];
        s += x * x;
    }
    out[idx] = sqrtf(s);
}

// ---------------- init u,v ----------------
__global__ void init_uv_kernel() {
    int idx = blockIdx.x * blockDim.x + threadIdx.x;
    if (idx < BATCH * MSZ) g_u[idx] = 1.0f / (float)MSZ;
    if (idx < BATCH * NSZ) g_v[idx] = 1.0f / (float)NSZ;
}

// ---------------- TF32 mma.sync GEMM + exp epilogue (unchanged) --------------
#define KC 16
#define SSTR 136
__global__ void __launch_bounds__(256, 2) gemm_mma_kernel(
        const float* __restrict__ Ae, const float* __restrict__ Be,
        const float* __restrict__ lptr) {
    __shared__ uint32_t sA[2][KC][SSTR];
    __shared__ uint32_t sB[2][KC][SSTR];

    int b = blockIdx.z;
    int m0 = blockIdx.y * 128;
    int n0 = blockIdx.x * 128;
    int tid = threadIdx.x;
    int wid = tid >> 5;
    int lane = tid & 31;
    int g = lane >> 2;
    int tig = lane & 3;
    int warp_m = (wid >> 2) * 64;
    int warp_n = (wid & 3) * 32;

    const float* Ab = Ae + (size_t)b * DIMD * MSZ;
    const float* Bb = Be + (size_t)b * DIMD * NSZ;

    int kr0 = tid >> 5;
    int c40 = tid & 31;
    int kr1 = (tid + 256) >> 5;
    int c41 = c40;

    float acc[4][4][4];
    #pragma unroll
    for (int mi = 0; mi < 4; mi++)
        #pragma unroll
        for (int ni = 0; ni < 4; ni++)
            #pragma unroll
            for (int q = 0; q < 4; q++) acc[mi][ni][q] = 0.0f;

    float4 ra0, ra1, rb0, rb1;

    ra0 = *(const float4*)&Ab[(size_t)kr0 * MSZ + m0 + c40 * 4];
    ra1 = *(const float4*)&Ab[(size_t)kr1 * MSZ + m0 + c41 * 4];
    rb0 = *(const float4*)&Bb[(size_t)kr0 * NSZ + n0 + c40 * 4];
    rb1 = *(const float4*)&Bb[(size_t)kr1 * NSZ + n0 + c41 * 4];
    {
        uint32_t* pa0 = &sA[0][kr0][c40 * 4];
        uint32_t* pa1 = &sA[0][kr1][c41 * 4];
        uint32_t* pb0 = &sB[0][kr0][c40 * 4];
        uint32_t* pb1 = &sB[0][kr1][c41 * 4];
        pa0[0] = f2tf(ra0.x); pa0[1] = f2tf(ra0.y); pa0[2] = f2tf(ra0.z); pa0[3] = f2tf(ra0.w);
        pa1[0] = f2tf(ra1.x); pa1[1] = f2tf(ra1.y); pa1[2] = f2tf(ra1.z); pa1[3] = f2tf(ra1.w);
        pb0[0] = f2tf(rb0.x); pb0[1] = f2tf(rb0.y); pb0[2] = f2tf(rb0.z); pb0[3] = f2tf(rb0.w);
        pb1[0] = f2tf(rb1.x); pb1[1] = f2tf(rb1.y); pb1[2] = f2tf(rb1.z); pb1[3] = f2tf(rb1.w);
    }
    __syncthreads();

    const int NCH = DIMD / KC;
    for (int c = 0; c < NCH; c++) {
        if (c + 1 < NCH) {
            int kb = (c + 1) * KC;
            ra0 = *(const float4*)&Ab[(size_t)(kb + kr0) * MSZ + m0 + c40 * 4];
            ra1 = *(const float4*)&Ab[(size_t)(kb + kr1) * MSZ + m0 + c41 * 4];
            rb0 = *(const float4*)&Bb[(size_t)(kb + kr0) * NSZ + n0 + c40 * 4];
            rb1 = *(const float4*)&Bb[(size_t)(kb + kr1) * NSZ + n0 + c41 * 4];
        }

        int cb = c & 1;
        #pragma unroll
        for (int ks = 0; ks < 2; ks++) {
            int k0 = ks * 8;
            uint32_t bf[4][2];
            #pragma unroll
            for (int ni = 0; ni < 4; ni++) {
                int nn = warp_n + ni * 8 + g;
                bf[ni][0] = sB[cb][k0 + tig][nn];
                bf[ni][1] = sB[cb][k0 + tig + 4][nn];
            }
            #pragma unroll
            for (int mi = 0; mi < 4; mi++) {
                int mm = warp_m + mi * 16 + g;
                uint32_t a0 = sA[cb][k0 + tig][mm];
                uint32_t a1 = sA[cb][k0 + tig][mm + 8];
                uint32_t a2 = sA[cb][k0 + tig + 4][mm];
                uint32_t a3 = sA[cb][k0 + tig + 4][mm + 8];
                #pragma unroll
                for (int ni = 0; ni < 4; ni++)
                    mma_tf32(acc[mi][ni], a0, a1, a2, a3, bf[ni][0], bf[ni][1]);
            }
        }

        if (c + 1 < NCH) {
            int nb = (c + 1) & 1;
            uint32_t* pa0 = &sA[nb][kr0][c40 * 4];
            uint32_t* pa1 = &sA[nb][kr1][c41 * 4];
            uint32_t* pb0 = &sB[nb][kr0][c40 * 4];
            uint32_t* pb1 = &sB[nb][kr1][c41 * 4];
            pa0[0] = f2tf(ra0.x); pa0[1] = f2tf(ra0.y); pa0[2] = f2tf(ra0.z); pa0[3] = f2tf(ra0.w);
            pa1[0] = f2tf(ra1.x); pa1[1] = f2tf(ra1.y); pa1[2] = f2tf(ra1.z); pa1[3] = f2tf(ra1.w);
            pb0[0] = f2tf(rb0.x); pb0[1] = f2tf(rb0.y); pb0[2] = f2tf(rb0.z); pb0[3] = f2tf(rb0.w);
            pb1[0] = f2tf(rb1.x); pb1[1] = f2tf(rb1.y); pb1[2] = f2tf(rb1.z); pb1[3] = f2tf(rb1.w);
        }
        __syncthreads();
    }

    float linv = 1.0f / fmaxf(lptr[0], 1e-8f);
    float n2r[8];
    #pragma unroll
    for (int ni = 0; ni < 4; ni++) {
        int nc = n0 + warp_n + ni * 8 + 2 * tig;
        n2r[ni * 2]     = g_n2[b * NSZ + nc];
        n2r[ni * 2 + 1] = g_n2[b * NSZ + nc + 1];
    }
    #pragma unroll
    for (int mi = 0; mi < 4; mi++) {
        #pragma unroll
        for (int half = 0; half < 2; half++) {
            int m = m0 + warp_m + mi * 16 + g + half * 8;
            float n1v = g_n1[b * MSZ + m];
            size_t rowoff = ((size_t)(b * MSZ + m)) * NSZ + n0 + warp_n;
            float* Krow = g_K + rowoff;
            uint32_t* Khrow = (uint32_t*)(g_Kh + rowoff);
            #pragma unroll
            for (int ni = 0; ni < 4; ni++) {
                float x0 = acc[mi][ni][half * 2 + 0];
                float x1 = acc[mi][ni][half * 2 + 1];
                float d0 = fmaxf(n1v * n2r[ni * 2], 1e-6f);
                float d1 = fmaxf(n1v * n2r[ni * 2 + 1], 1e-6f);
                float o0 = expf(-(1.0f - x0 / d0) * linv);
                float o1 = expf(-(1.0f - x1 / d1) * linv);
                *(float2*)&Krow[ni * 8 + 2 * tig] = make_float2(o0, o1);
                Khrow[ni * 4 + tig] = pack_bf16x2(o0, o1);
            }
        }
    }
}

// ---------------- fused Sinkhorn (pipelined phase A, L2-hit phase B) ----------
// Phase A: per warp, 4 rows; register double-buffer prefetch (MLP 8); all four
// shfl-reduction chains done together (ILP-4); powf x4 once.
// Phase B: column partials re-read K (L2 hit), unroll 8 for MLP.
__global__ void __launch_bounds__(256) sink_fused_kernel(
        const float* __restrict__ lptr, const float* __restrict__ rptr) {
    __shared__ float sv[1024];
    __shared__ float su[32];
    int b = blockIdx.y;
    int m0 = blockIdx.x * 32;
    int tid = threadIdx.x;
    int wid = tid >> 5;
    int lane = tid & 31;

    // stage v to SMEM once
    ((float4*)sv)[tid] = *(const float4*)&g_v[b * NSZ + tid * 4];
    __syncthreads();

    float lv = lptr[0], rv = rptr[0];
    float fi = rv / fmaxf(rv + lv, 1e-8f);
    float a = 1.0f / (float)MSZ;
    const float4* sv4 = (const float4*)sv;

    int rbase = b * MSZ + m0 + (wid << 2);
    float s[4];
    uint4 buf[2][4];
    {
        const uint4* K0 = (const uint4*)(g_Kh + (size_t)(rbase + 0) * NSZ);
        const uint4* K1 = (const uint4*)(g_Kh + (size_t)(rbase + 1) * NSZ);
        #pragma unroll
        for (int j = 0; j < 4; j++) buf[0][j] = K0[j * 32 + lane];
        #pragma unroll
        for (int j = 0; j < 4; j++) buf[1][j] = K1[j * 32 + lane];
    }
    #pragma unroll
    for (int rr = 0; rr < 4; rr++) {
        uint4 kk[4];
        #pragma unroll
        for (int j = 0; j < 4; j++) kk[j] = buf[rr & 1][j];
        if (rr < 2) {
            const uint4* Kn = (const uint4*)(g_Kh + (size_t)(rbase + rr + 2) * NSZ);
            #pragma unroll
            for (int j = 0; j < 4; j++) buf[rr & 1][j] = Kn[j * 32 + lane];
        }
        float acc = 0.0f;
        #pragma unroll
        for (int j = 0; j < 4; j++) {
            int sl = j * 32 + lane;
            float4 va = sv4[sl * 2];
            float4 vb = sv4[sl * 2 + 1];
            acc += bf_lo(kk[j].x) * va.x + bf_hi(kk[j].x) * va.y
                 + bf_lo(kk[j].y) * va.z + bf_hi(kk[j].y) * va.w
                 + bf_lo(kk[j].z) * vb.x + bf_hi(kk[j].z) * vb.y
                 + bf_lo(kk[j].w) * vb.z + bf_hi(kk[j].w) * vb.w;
        }
        s[rr] = acc;
    }
    // four reduction chains together (ILP overlaps shfl latency)
    #pragma unroll
    for (int o = 16; o > 0; o >>= 1) {
        #pragma unroll
        for (int rr = 0; rr < 4; rr++)
            s[rr] += __shfl_down_sync(0xffffffffu, s[rr], o);
    }
    if (lane == 0) {
        #pragma unroll
        for (int rr = 0; rr < 4; rr++) {
            float uu = powf(a / fmaxf(s[rr], 1e-8f), fi);
            g_u[rbase + rr] = uu;
            su[(wid << 2) | rr] = uu;
        }
    }
    __syncthreads();

    // Phase B: thread owns 4 cols (uint2 = 4 bf16) over the 32 rows (L2 hits)
    const uint16_t* Kbh = g_Kh + (size_t)(b * MSZ + m0) * NSZ;
    float4 acc = make_float4(0.f, 0.f, 0.f, 0.f);
    #pragma unroll 8
    for (int r = 0; r < 32; r++) {
        float uu = su[r];
        uint2 kk = *(const uint2*)&Kbh[(size_t)r * NSZ + tid * 4];
        acc.x += uu * bf_lo(kk.x);
        acc.y += uu * bf_hi(kk.x);
        acc.z += uu * bf_lo(kk.y);
        acc.w += uu * bf_hi(kk.y);
    }
    *(float4*)&g_vpart[((size_t)blockIdx.x * BATCH + b) * NSZ + tid * 4] = acc;
}

// ---------------- v = (b / clip(colsum, eps))^fi ----------------
__global__ void sink_vpow_kernel(const float* __restrict__ lptr, const float* __restrict__ rptr) {
    int idx = blockIdx.x * blockDim.x + threadIdx.x;
    int b = idx >> 10;
    int n = idx & 1023;
    float s = 0.0f;
    #pragma unroll
    for (int z = 0; z < MSPLIT; z++)
        s += g_vpart[((size_t)z * BATCH + b) * NSZ + n];
    float lv = lptr[0], rv = rptr[0];
    float fi = rv / fmaxf(rv + lv, 1e-8f);
    float bb = 1.0f / (float)NSZ;
    g_v[idx] = powf(bb / fmaxf(s, 1e-8f), fi);
}

// ---------------- P = u*K*v, row sums, weighted_ref (fp32 K, one pass) -------
__global__ void compute_P_kernel(const float* __restrict__ tgt, float* __restrict__ Pout) {
    __shared__ float sred[32];
    int bm = blockIdx.x;
    int b = bm >> 10;
    float uu = g_u[bm];
    const float4* Krow = (const float4*)(g_K + (size_t)bm * NSZ);
    const float4* vrow = (const float4*)(g_v + b * NSZ);
    float4* Prow = (float4*)(Pout + (size_t)bm * NSZ);
    const float4* t0 = (const float4*)(tgt + ((size_t)b * 3 + 0) * NSZ);
    const float4* t1 = (const float4*)(tgt + ((size_t)b * 3 + 1) * NSZ);
    const float4* t2 = (const float4*)(tgt + ((size_t)b * 3 + 2) * NSZ);

    int t = threadIdx.x;
    float4 kk = Krow[t];
    float4 vv = vrow[t];
    float4 p;
    p.x = uu * kk.x * vv.x;
    p.y = uu * kk.y * vv.y;
    p.z = uu * kk.z * vv.z;
    p.w = uu * kk.w * vv.w;
    Prow[t] = p;

    float4 a0 = t0[t], a1 = t1[t], a2 = t2[t];
    float rs = p.x + p.y + p.z + p.w;
    float w0 = p.x * a0.x + p.y * a0.y + p.z * a0.z + p.w * a0.w;
    float w1 = p.x * a1.x + p.y * a1.y + p.z * a1.z + p.w * a1.w;
    float w2 = p.x * a2.x + p.y * a2.y + p.z * a2.z + p.w * a2.w;

    rs = blockReduceB(rs, sred);
    w0 = blockReduceB(w0, sred);
    w1 = blockReduceB(w1, sred);
    w2 = blockReduceB(w2, sred);
    if (threadIdx.x == 0) {
        g_rowS[bm] = rs;
        float inv = 1.0f / (rs + 1e-6f);
        g_wref[bm * 3 + 0] = w0 * inv;
        g_wref[bm * 3 + 1] = w1 * inv;
        g_wref[bm * 3 + 2] = w2 * inv;
    }
}

// ---------------- per-batch centroids + covariance ----------------
__global__ void cov_kernel(const float* __restrict__ src) {
    __shared__ float sred[32];
    int b = blockIdx.x;
    int t = threadIdx.x;

    float s = 0.0f;
    for (int m = t; m < MSZ; m += 256) s += g_rowS[b * MSZ + m];
    float S = blockReduceB(s, sred);
    float inv = 1.0f / (S + 1e-6f);

    float ca[3] = {0, 0, 0}, cb[3] = {0, 0, 0};
    for (int m = t; m < MSZ; m += 256) {
        float w = g_rowS[b * MSZ + m] * inv;
        #pragma unroll
        for (int d = 0; d < 3; d++) {
            ca[d] += w * src[((size_t)b * 3 + d) * MSZ + m];
            cb[d] += w * g_wref[(b * MSZ + m) * 3 + d];
        }
    }
    float CA[3], CB[3];
    #pragma unroll
    for (int d = 0; d < 3; d++) CA[d] = blockReduceB(ca[d], sred);
    #pragma unroll
    for (int d = 0; d < 3; d++) CB[d] = blockReduceB(cb[d], sred);

    float cv[9] = {0, 0, 0, 0, 0, 0, 0, 0, 0};
    for (int m = t; m < MSZ; m += 256) {
        float w = g_rowS[b * MSZ + m] * inv;
        float ac[3], bc[3];
        #pragma unroll
        for (int d = 0; d < 3; d++) {
            ac[d] = src[((size_t)b * 3 + d) * MSZ + m] - CA[d];
            bc[d] = g_wref[(b * MSZ + m) * 3 + d] - CB[d];
        }
        #pragma unroll
        for (int i = 0; i < 3; i++)
            #pragma unroll
            for (int j = 0; j < 3; j++)
                cv[i * 3 + j] += ac[i] * bc[j] * w;
    }
    #pragma unroll
    for (int k = 0; k < 9; k++) {
        float r = blockReduceB(cv[k], sred);
        if (t == 0) g_cov[b * 9 + k] = r;
    }
    if (t == 0) {
        #pragma unroll
        for (int d = 0; d < 3; d++) { g_ca[b * 3 + d] = CA[d]; g_cb[b * 3 + d] = CB[d]; }
    }
}

// ---------------- 3x3 SVD (fp64 Jacobi) + Kabsch R,t ----------------
__global__ void svd_kernel(float* __restrict__ out) {
    int b = threadIdx.x;
    if (b >= BATCH) return;

    double A[3][3];
    #pragma unroll
    for (int i = 0; i < 3; i++)
        #pragma unroll
        for (int j = 0; j < 3; j++)
            A[i][j] = (double)g_cov[b * 9 + i * 3 + j];

    double S[3][3];
    #pragma unroll
    for (int i = 0; i < 3; i++)
        #pragma unroll
        for (int j = 0; j < 3; j++) {
            double acc = 0.0;
            #pragma unroll
            for (int k = 0; k < 3; k++) acc += A[k][i] * A[k][j];
            S[i][j] = acc;
        }

    double V[3][3] = {{1, 0, 0}, {0, 1, 0}, {0, 0, 1}};
    const int PP[3] = {0, 0, 1};
    const int QQ[3] = {1, 2, 2};
    for (int sweep = 0; sweep < 20; sweep++) {
        for (int r = 0; r < 3; r++) {
            int p = PP[r], q = QQ[r];
            double apq = S[p][q];
            if (apq == 0.0) continue;
            double theta = (S[q][q] - S[p][p]) / (2.0 * apq);
            double tt = copysign(1.0, theta) / (fabs(theta) + sqrt(1.0 + theta * theta));
            double c = 1.0 / sqrt(1.0 + tt * tt);
            double sn = tt * c;
            for (int k = 0; k < 3; k++) {
                double skp = S[k][p], skq = S[k][q];
                S[k][p] = c * skp - sn * skq;
                S[k][q] = sn * skp + c * skq;
            }
            for (int k = 0; k < 3; k++) {
                double spk = S[p][k], sqk = S[q][k];
                S[p][k] = c * spk - sn * sqk;
                S[q][k] = sn * spk + c * sqk;
            }
            for (int k = 0; k < 3; k++) {
                double vkp = V[k][p], vkq = V[k][q];
                V[k][p] = c * vkp - sn * vkq;
                V[k][q] = sn * vkp + c * vkq;
            }
        }
    }

    double ev[3] = {S[0][0], S[1][1], S[2][2]};
    int idx[3] = {0, 1, 2};
    for (int i = 0; i < 2; i++)
        for (int j = i + 1; j < 3; j++)
            if (ev[idx[j]] > ev[idx[i]]) { int tmp = idx[i]; idx[i] = idx[j]; idx[j] = tmp; }

    double Vs[3][3];
    #pragma unroll
    for (int k = 0; k < 3; k++)
        for (int i = 0; i < 3; i++)
            Vs[k][i] = V[k][idx[i]];

    double U[3][3];
    double nrm[3];
    for (int i = 0; i < 3; i++) {
        double u0 = A[0][0] * Vs[0][i] + A[0][1] * Vs[1][i] + A[0][2] * Vs[2][i];
        double u1 = A[1][0] * Vs[0][i] + A[1][1] * Vs[1][i] + A[1][2] * Vs[2][i];
        double u2 = A[2][0] * Vs[0][i] + A[2][1] * Vs[1][i] + A[2][2] * Vs[2][i];
        double nm = sqrt(u0 * u0 + u1 * u1 + u2 * u2);
        nrm[i] = nm;
        double in = (nm > 1e-300) ? 1.0 / nm : 0.0;
        U[0][i] = u0 * in; U[1][i] = u1 * in; U[2][i] = u2 * in;
    }
    if (nrm[2] < 1e-12 * fmax(nrm[0], 1e-300)) {
        U[0][2] = U[1][0] * U[2][1] - U[2][0] * U[1][1];
        U[1][2] = U[2][0] * U[0][1] - U[0][0] * U[2][1];
        U[2][2] = U[0][0] * U[1][1] - U[1][0] * U[0][1];
    }

    double R[3][3];
    for (int i = 0; i < 3; i++)
        for (int j = 0; j < 3; j++)
            R[i][j] = Vs[i][0] * U[j][0] + Vs[i][1] * U[j][1] + Vs[i][2] * U[j][2];

    double det = R[0][0] * (R[1][1] * R[2][2] - R[1][2] * R[2][1])
               - R[0][1] * (R[1][0] * R[2][2] - R[1][2] * R[2][0])
               + R[0][2] * (R[1][0] * R[2][1] - R[1][1] * R[2][0]);
    if (!(det > 0.0)) {
        for (int i = 0; i < 3; i++)
            for (int j = 0; j < 3; j++)
                R[i][j] -= 2.0 * Vs[i][2] * U[j][2];
    }

    double ca[3] = {(double)g_ca[b * 3], (double)g_ca[b * 3 + 1], (double)g_ca[b * 3 + 2]};
    double cb[3] = {(double)g_cb[b * 3], (double)g_cb[b * 3 + 1], (double)g_cb[b * 3 + 2]};
    double tv[3];
    for (int i = 0; i < 3; i++)
        tv[i] = -(R[i][0] * ca[0] + R[i][1] * ca[1] + R[i][2] * ca[2]) + cb[i];

    for (int i = 0; i < 3; i++)
        for (int j = 0; j < 3; j++)
            out[b * 9 + i * 3 + j] = (float)R[i][j];
    for (int i = 0; i < 3; i++)
        out[288 + b * 3 + i] = (float)tv[i];
}

// ---------------- launch ----------------
extern "C" void kernel_launch(void* const* d_in, const int* in_sizes, int n_in,
                              void* d_out, int out_size) {
    const float* src_emb = (const float*)d_in[0];
    const float* tgt_emb = (const float*)d_in[1];
    const float* src     = (const float*)d_in[2];
    const float* tgt     = (const float*)d_in[3];
    const float* lptr    = (const float*)d_in[4];
    const float* rptr    = (const float*)d_in[5];
    float* out = (float*)d_out;
    float* Pout = out + BATCH * 9 + BATCH * 3;

    // launch order: first sink_fused is the 4th launch (ncu capture slot)
    dim3 ngrid(BATCH * MSZ / 256, 2);
    norms2_kernel<<<ngrid, 256>>>(src_emb, tgt_emb);
    init_uv_kernel<<<(BATCH * MSZ) / 256, 256>>>();

    dim3 ggrid(NSZ / 128, MSZ / 128, BATCH);
    gemm_mma_kernel<<<ggrid, 256>>>(src_emb, tgt_emb, lptr);

    for (int it = 0; it < SINK_ITERS; it++) {
        dim3 sgrid(MSZ / 32, BATCH);
        sink_fused_kernel<<<sgrid, 256>>>(lptr, rptr);
        sink_vpow_kernel<<<(BATCH * NSZ) / 256, 256>>>(lptr, rptr);
    }

    compute_P_kernel<<<BATCH * MSZ, 256>>>(tgt, Pout);
    cov_kernel<<<BATCH, 256>>>(src);
    svd_kernel<<<1, 32>>>(out);
}

// round 14
// speedup vs baseline: 1.0996x; 1.0067x over previous
#include <cuda_runtime.h>
#include <math.h>
#include <stdint.h>

#define BATCH 32
#define DIMD  512
#define MSZ   1024
#define NSZ   1024
#define SINK_ITERS 5
#define MSPLIT 32

// ---------------- device scratch (static: no allocations) ----------------
__device__ float    g_K [(size_t)BATCH * MSZ * NSZ];   // 134 MB fp32 kernel matrix
__device__ uint16_t g_Kh[(size_t)BATCH * MSZ * NSZ];   //  67 MB bf16 shadow (Sinkhorn reads)
__device__ float g_n1[BATCH * MSZ];
__device__ float g_n2[BATCH * NSZ];
__device__ float g_u[BATCH * MSZ];
__device__ float g_v[BATCH * NSZ];
__device__ float g_vpart[2][(size_t)MSPLIT * BATCH * NSZ];  // double-buffered
__device__ float g_rowS[BATCH * MSZ];
__device__ float g_wref[BATCH * MSZ * 3];
__device__ float g_cov[BATCH * 9];
__device__ float g_ca[BATCH * 3];
__device__ float g_cb[BATCH * 3];

// ---------------- PTX helpers ----------------
__device__ __forceinline__ uint32_t f2tf(float x) {
    uint32_t r;
    asm("cvt.rna.tf32.f32 %0, %1;" : "=r"(r) : "f"(x));
    return r;
}
__device__ __forceinline__ uint32_t pack_bf16x2(float lo, float hi) {
    uint32_t r;
    asm("cvt.rn.bf16x2.f32 %0, %1, %2;" : "=r"(r) : "f"(hi), "f"(lo));
    return r;
}
__device__ __forceinline__ float bf_lo(uint32_t u) { return __uint_as_float(u << 16); }
__device__ __forceinline__ float bf_hi(uint32_t u) { return __uint_as_float(u & 0xFFFF0000u); }

__device__ __forceinline__ void mma_tf32(float* c, uint32_t a0, uint32_t a1,
                                         uint32_t a2, uint32_t a3,
                                         uint32_t b0, uint32_t b1) {
    asm volatile(
        "mma.sync.aligned.m16n8k8.row.col.f32.tf32.tf32.f32 "
        "{%0,%1,%2,%3},{%4,%5,%6,%7},{%8,%9},{%0,%1,%2,%3};"
        : "+f"(c[0]), "+f"(c[1]), "+f"(c[2]), "+f"(c[3])
        : "r"(a0), "r"(a1), "r"(a2), "r"(a3), "r"(b0), "r"(b1));
}

// ---------------- generic helpers ----------------
__device__ __forceinline__ float blockReduceB(float v, volatile float* sred) {
    int lane = threadIdx.x & 31;
    int wid = threadIdx.x >> 5;
    #pragma unroll
    for (int o = 16; o > 0; o >>= 1) v += __shfl_down_sync(0xffffffffu, v, o);
    if (lane == 0) sred[wid] = v;
    __syncthreads();
    if (threadIdx.x < 32) {
        int nw = (blockDim.x + 31) >> 5;
        float x = (threadIdx.x < nw) ? sred[threadIdx.x] : 0.0f;
        #pragma unroll
        for (int o = 16; o > 0; o >>= 1) x += __shfl_down_sync(0xffffffffu, x, o);
        if (threadIdx.x == 0) sred[0] = x;
    }
    __syncthreads();
    float r = sred[0];
    __syncthreads();
    return r;
}

// ---------------- fused norms: grid.y selects src/tgt embedding --------------
__global__ void norms2_kernel(const float* __restrict__ E1, const float* __restrict__ E2) {
    int idx = blockIdx.x * blockDim.x + threadIdx.x;
    const float* E = blockIdx.y ? E2 : E1;
    float* out = blockIdx.y ? g_n2 : g_n1;
    int b = idx >> 10;
    int m = idx & 1023;
    const float* p = E + (size_t)b * DIMD * MSZ + m;
    float s = 0.0f;
    #pragma unroll 8
    for (int d = 0; d < DIMD; d++) {
        float x = p[(size_t)d * MSZ];
        s += x * x;
    }
    out[idx] = sqrtf(s);
}

// ---------------- init u ----------------
__global__ void init_uv_kernel() {
    int idx = blockIdx.x * blockDim.x + threadIdx.x;
    if (idx < BATCH * MSZ) g_u[idx] = 1.0f / (float)MSZ;
    if (idx < BATCH * NSZ) g_v[idx] = 1.0f / (float)NSZ;
}

// ---------------- TF32 mma.sync GEMM + exp epilogue (unchanged) --------------
#define KC 16
#define SSTR 136
__global__ void __launch_bounds__(256, 2) gemm_mma_kernel(
        const float* __restrict__ Ae, const float* __restrict__ Be,
        const float* __restrict__ lptr) {
    __shared__ uint32_t sA[2][KC][SSTR];
    __shared__ uint32_t sB[2][KC][SSTR];

    int b = blockIdx.z;
    int m0 = blockIdx.y * 128;
    int n0 = blockIdx.x * 128;
    int tid = threadIdx.x;
    int wid = tid >> 5;
    int lane = tid & 31;
    int g = lane >> 2;
    int tig = lane & 3;
    int warp_m = (wid >> 2) * 64;
    int warp_n = (wid & 3) * 32;

    const float* Ab = Ae + (size_t)b * DIMD * MSZ;
    const float* Bb = Be + (size_t)b * DIMD * NSZ;

    int kr0 = tid >> 5;
    int c40 = tid & 31;
    int kr1 = (tid + 256) >> 5;
    int c41 = c40;

    float acc[4][4][4];
    #pragma unroll
    for (int mi = 0; mi < 4; mi++)
        #pragma unroll
        for (int ni = 0; ni < 4; ni++)
            #pragma unroll
            for (int q = 0; q < 4; q++) acc[mi][ni][q] = 0.0f;

    float4 ra0, ra1, rb0, rb1;

    ra0 = *(const float4*)&Ab[(size_t)kr0 * MSZ + m0 + c40 * 4];
    ra1 = *(const float4*)&Ab[(size_t)kr1 * MSZ + m0 + c41 * 4];
    rb0 = *(const float4*)&Bb[(size_t)kr0 * NSZ + n0 + c40 * 4];
    rb1 = *(const float4*)&Bb[(size_t)kr1 * NSZ + n0 + c41 * 4];
    {
        uint32_t* pa0 = &sA[0][kr0][c40 * 4];
        uint32_t* pa1 = &sA[0][kr1][c41 * 4];
        uint32_t* pb0 = &sB[0][kr0][c40 * 4];
        uint32_t* pb1 = &sB[0][kr1][c41 * 4];
        pa0[0] = f2tf(ra0.x); pa0[1] = f2tf(ra0.y); pa0[2] = f2tf(ra0.z); pa0[3] = f2tf(ra0.w);
        pa1[0] = f2tf(ra1.x); pa1[1] = f2tf(ra1.y); pa1[2] = f2tf(ra1.z); pa1[3] = f2tf(ra1.w);
        pb0[0] = f2tf(rb0.x); pb0[1] = f2tf(rb0.y); pb0[2] = f2tf(rb0.z); pb0[3] = f2tf(rb0.w);
        pb1[0] = f2tf(rb1.x); pb1[1] = f2tf(rb1.y); pb1[2] = f2tf(rb1.z); pb1[3] = f2tf(rb1.w);
    }
    __syncthreads();

    const int NCH = DIMD / KC;
    for (int c = 0; c < NCH; c++) {
        if (c + 1 < NCH) {
            int kb = (c + 1) * KC;
            ra0 = *(const float4*)&Ab[(size_t)(kb + kr0) * MSZ + m0 + c40 * 4];
            ra1 = *(const float4*)&Ab[(size_t)(kb + kr1) * MSZ + m0 + c41 * 4];
            rb0 = *(const float4*)&Bb[(size_t)(kb + kr0) * NSZ + n0 + c40 * 4];
            rb1 = *(const float4*)&Bb[(size_t)(kb + kr1) * NSZ + n0 + c41 * 4];
        }

        int cb = c & 1;
        #pragma unroll
        for (int ks = 0; ks < 2; ks++) {
            int k0 = ks * 8;
            uint32_t bf[4][2];
            #pragma unroll
            for (int ni = 0; ni < 4; ni++) {
                int nn = warp_n + ni * 8 + g;
                bf[ni][0] = sB[cb][k0 + tig][nn];
                bf[ni][1] = sB[cb][k0 + tig + 4][nn];
            }
            #pragma unroll
            for (int mi = 0; mi < 4; mi++) {
                int mm = warp_m + mi * 16 + g;
                uint32_t a0 = sA[cb][k0 + tig][mm];
                uint32_t a1 = sA[cb][k0 + tig][mm + 8];
                uint32_t a2 = sA[cb][k0 + tig + 4][mm];
                uint32_t a3 = sA[cb][k0 + tig + 4][mm + 8];
                #pragma unroll
                for (int ni = 0; ni < 4; ni++)
                    mma_tf32(acc[mi][ni], a0, a1, a2, a3, bf[ni][0], bf[ni][1]);
            }
        }

        if (c + 1 < NCH) {
            int nb = (c + 1) & 1;
            uint32_t* pa0 = &sA[nb][kr0][c40 * 4];
            uint32_t* pa1 = &sA[nb][kr1][c41 * 4];
            uint32_t* pb0 = &sB[nb][kr0][c40 * 4];
            uint32_t* pb1 = &sB[nb][kr1][c41 * 4];
            pa0[0] = f2tf(ra0.x); pa0[1] = f2tf(ra0.y); pa0[2] = f2tf(ra0.z); pa0[3] = f2tf(ra0.w);
            pa1[0] = f2tf(ra1.x); pa1[1] = f2tf(ra1.y); pa1[2] = f2tf(ra1.z); pa1[3] = f2tf(ra1.w);
            pb0[0] = f2tf(rb0.x); pb0[1] = f2tf(rb0.y); pb0[2] = f2tf(rb0.z); pb0[3] = f2tf(rb0.w);
            pb1[0] = f2tf(rb1.x); pb1[1] = f2tf(rb1.y); pb1[2] = f2tf(rb1.z); pb1[3] = f2tf(rb1.w);
        }
        __syncthreads();
    }

    float linv = 1.0f / fmaxf(lptr[0], 1e-8f);
    float n2r[8];
    #pragma unroll
    for (int ni = 0; ni < 4; ni++) {
        int nc = n0 + warp_n + ni * 8 + 2 * tig;
        n2r[ni * 2]     = g_n2[b * NSZ + nc];
        n2r[ni * 2 + 1] = g_n2[b * NSZ + nc + 1];
    }
    #pragma unroll
    for (int mi = 0; mi < 4; mi++) {
        #pragma unroll
        for (int half = 0; half < 2; half++) {
            int m = m0 + warp_m + mi * 16 + g + half * 8;
            float n1v = g_n1[b * MSZ + m];
            size_t rowoff = ((size_t)(b * MSZ + m)) * NSZ + n0 + warp_n;
            float* Krow = g_K + rowoff;
            uint32_t* Khrow = (uint32_t*)(g_Kh + rowoff);
            #pragma unroll
            for (int ni = 0; ni < 4; ni++) {
                float x0 = acc[mi][ni][half * 2 + 0];
                float x1 = acc[mi][ni][half * 2 + 1];
                float d0 = fmaxf(n1v * n2r[ni * 2], 1e-6f);
                float d1 = fmaxf(n1v * n2r[ni * 2 + 1], 1e-6f);
                float o0 = expf(-(1.0f - x0 / d0) * linv);
                float o1 = expf(-(1.0f - x1 / d1) * linv);
                *(float2*)&Krow[ni * 8 + 2 * tig] = make_float2(o0, o1);
                Khrow[ni * 4 + tig] = pack_bf16x2(o0, o1);
            }
        }
    }
}

// ---------------- fused Sinkhorn iteration (phase0: v, A: u, B: vpart) -------
// Phase 0: compute this iteration's v from previous vpart buffer (or b-init).
// Same z-summation order as old vpow -> bit-identical v. Double-buffered vpart.
__global__ void __launch_bounds__(256) sink_fused_kernel(
        const float* __restrict__ lptr, const float* __restrict__ rptr, int it) {
    __shared__ float sv[1024];
    __shared__ float su[32];
    int b = blockIdx.y;
    int m0 = blockIdx.x * 32;
    int tid = threadIdx.x;
    int wid = tid >> 5;
    int lane = tid & 31;

    float lv = lptr[0], rv = rptr[0];
    float fi = rv / fmaxf(rv + lv, 1e-8f);
    float a = 1.0f / (float)MSZ;
    float bb = 1.0f / (float)NSZ;

    // Phase 0: materialize v for this iteration
    if (it == 0) {
        ((float4*)sv)[tid] = make_float4(bb, bb, bb, bb);
    } else {
        const float* vp = g_vpart[(it - 1) & 1];
        float4 s4 = make_float4(0.f, 0.f, 0.f, 0.f);
        #pragma unroll
        for (int z = 0; z < MSPLIT; z++) {
            float4 p4 = *(const float4*)&vp[((size_t)z * BATCH + b) * NSZ + tid * 4];
            s4.x += p4.x; s4.y += p4.y; s4.z += p4.z; s4.w += p4.w;
        }
        float4 v4;
        v4.x = powf(bb / fmaxf(s4.x, 1e-8f), fi);
        v4.y = powf(bb / fmaxf(s4.y, 1e-8f), fi);
        v4.z = powf(bb / fmaxf(s4.z, 1e-8f), fi);
        v4.w = powf(bb / fmaxf(s4.w, 1e-8f), fi);
        ((float4*)sv)[tid] = v4;
    }
    __syncthreads();

    const float4* sv4 = (const float4*)sv;

    // Phase A: pipelined row sums -> u
    int rbase = b * MSZ + m0 + (wid << 2);
    float s[4];
    uint4 buf[2][4];
    {
        const uint4* K0 = (const uint4*)(g_Kh + (size_t)(rbase + 0) * NSZ);
        const uint4* K1 = (const uint4*)(g_Kh + (size_t)(rbase + 1) * NSZ);
        #pragma unroll
        for (int j = 0; j < 4; j++) buf[0][j] = K0[j * 32 + lane];
        #pragma unroll
        for (int j = 0; j < 4; j++) buf[1][j] = K1[j * 32 + lane];
    }
    #pragma unroll
    for (int rr = 0; rr < 4; rr++) {
        uint4 kk[4];
        #pragma unroll
        for (int j = 0; j < 4; j++) kk[j] = buf[rr & 1][j];
        if (rr < 2) {
            const uint4* Kn = (const uint4*)(g_Kh + (size_t)(rbase + rr + 2) * NSZ);
            #pragma unroll
            for (int j = 0; j < 4; j++) buf[rr & 1][j] = Kn[j * 32 + lane];
        }
        float acc = 0.0f;
        #pragma unroll
        for (int j = 0; j < 4; j++) {
            int sl = j * 32 + lane;
            float4 va = sv4[sl * 2];
            float4 vb = sv4[sl * 2 + 1];
            acc += bf_lo(kk[j].x) * va.x + bf_hi(kk[j].x) * va.y
                 + bf_lo(kk[j].y) * va.z + bf_hi(kk[j].y) * va.w
                 + bf_lo(kk[j].z) * vb.x + bf_hi(kk[j].z) * vb.y
                 + bf_lo(kk[j].w) * vb.z + bf_hi(kk[j].w) * vb.w;
        }
        s[rr] = acc;
    }
    #pragma unroll
    for (int o = 16; o > 0; o >>= 1) {
        #pragma unroll
        for (int rr = 0; rr < 4; rr++)
            s[rr] += __shfl_down_sync(0xffffffffu, s[rr], o);
    }
    if (lane == 0) {
        #pragma unroll
        for (int rr = 0; rr < 4; rr++) {
            float uu = powf(a / fmaxf(s[rr], 1e-8f), fi);
            g_u[rbase + rr] = uu;
            su[(wid << 2) | rr] = uu;
        }
    }
    __syncthreads();

    // Phase B: column partials (L2 hits) into this iteration's vpart buffer
    const uint16_t* Kbh = g_Kh + (size_t)(b * MSZ + m0) * NSZ;
    float4 acc = make_float4(0.f, 0.f, 0.f, 0.f);
    #pragma unroll 8
    for (int r = 0; r < 32; r++) {
        float uu = su[r];
        uint2 kk = *(const uint2*)&Kbh[(size_t)r * NSZ + tid * 4];
        acc.x += uu * bf_lo(kk.x);
        acc.y += uu * bf_hi(kk.x);
        acc.z += uu * bf_lo(kk.y);
        acc.w += uu * bf_hi(kk.y);
    }
    *(float4*)&g_vpart[it & 1][((size_t)blockIdx.x * BATCH + b) * NSZ + tid * 4] = acc;
}

// ---------------- final v materialization ----------------
__global__ void sink_vpow_kernel(const float* __restrict__ lptr,
                                 const float* __restrict__ rptr, int srcbuf) {
    int idx = blockIdx.x * blockDim.x + threadIdx.x;
    int b = idx >> 10;
    int n = idx & 1023;
    const float* vp = g_vpart[srcbuf];
    float s = 0.0f;
    #pragma unroll
    for (int z = 0; z < MSPLIT; z++)
        s += vp[((size_t)z * BATCH + b) * NSZ + n];
    float lv = lptr[0], rv = rptr[0];
    float fi = rv / fmaxf(rv + lv, 1e-8f);
    float bb = 1.0f / (float)NSZ;
    g_v[idx] = powf(bb / fmaxf(s, 1e-8f), fi);
}

// ---------------- P = u*K*v (MLP-4: 4 rows/block, 64 lanes/row) --------------
__global__ void __launch_bounds__(256) compute_P_kernel(
        const float* __restrict__ tgt, float* __restrict__ Pout) {
    __shared__ float sred[8][4];
    int blk = blockIdx.x;            // handles rows blk*4 .. blk*4+3
    int tid = threadIdx.x;
    int wpair = tid >> 6;            // 0..3 -> row within block
    int lp = tid & 63;               // lane within 64-lane pair
    int wid = tid >> 5;
    int lane = tid & 31;
    int bm = blk * 4 + wpair;
    int b = bm >> 10;

    float uu = g_u[bm];
    const float4* Krow = (const float4*)(g_K + (size_t)bm * NSZ);
    const float4* vrow = (const float4*)(g_v + b * NSZ);
    float4* Prow = (float4*)(Pout + (size_t)bm * NSZ);
    const float4* t0 = (const float4*)(tgt + ((size_t)b * 3 + 0) * NSZ);
    const float4* t1 = (const float4*)(tgt + ((size_t)b * 3 + 1) * NSZ);
    const float4* t2 = (const float4*)(tgt + ((size_t)b * 3 + 2) * NSZ);

    float rs = 0.f, w0 = 0.f, w1 = 0.f, w2 = 0.f;
    // 4 independent float4 loads per thread (MLP 4)
    float4 kk[4];
    #pragma unroll
    for (int q = 0; q < 4; q++) kk[q] = Krow[lp + 64 * q];
    #pragma unroll
    for (int q = 0; q < 4; q++) {
        int sl = lp + 64 * q;
        float4 vv = vrow[sl];
        float4 p;
        p.x = uu * kk[q].x * vv.x;
        p.y = uu * kk[q].y * vv.y;
        p.z = uu * kk[q].z * vv.z;
        p.w = uu * kk[q].w * vv.w;
        Prow[sl] = p;
        float4 a0 = t0[sl], a1 = t1[sl], a2 = t2[sl];
        rs += p.x + p.y + p.z + p.w;
        w0 += p.x * a0.x + p.y * a0.y + p.z * a0.z + p.w * a0.w;
        w1 += p.x * a1.x + p.y * a1.y + p.z * a1.z + p.w * a1.w;
        w2 += p.x * a2.x + p.y * a2.y + p.z * a2.z + p.w * a2.w;
    }
    // warp reduce (4 vars together for ILP)
    #pragma unroll
    for (int o = 16; o > 0; o >>= 1) {
        rs += __shfl_down_sync(0xffffffffu, rs, o);
        w0 += __shfl_down_sync(0xffffffffu, w0, o);
        w1 += __shfl_down_sync(0xffffffffu, w1, o);
        w2 += __shfl_down_sync(0xffffffffu, w2, o);
    }
    if (lane == 0) {
        sred[wid][0] = rs; sred[wid][1] = w0; sred[wid][2] = w1; sred[wid][3] = w2;
    }
    __syncthreads();
    if (lp == 0) {
        int wa = 2 * wpair, wb = 2 * wpair + 1;
        float RS = sred[wa][0] + sred[wb][0];
        float W0 = sred[wa][1] + sred[wb][1];
        float W1 = sred[wa][2] + sred[wb][2];
        float W2 = sred[wa][3] + sred[wb][3];
        g_rowS[bm] = RS;
        float inv = 1.0f / (RS + 1e-6f);
        g_wref[bm * 3 + 0] = W0 * inv;
        g_wref[bm * 3 + 1] = W1 * inv;
        g_wref[bm * 3 + 2] = W2 * inv;
    }
}

// ---------------- per-batch centroids + covariance ----------------
__global__ void cov_kernel(const float* __restrict__ src) {
    __shared__ float sred[32];
    int b = blockIdx.x;
    int t = threadIdx.x;

    float s = 0.0f;
    for (int m = t; m < MSZ; m += 256) s += g_rowS[b * MSZ + m];
    float S = blockReduceB(s, sred);
    float inv = 1.0f / (S + 1e-6f);

    float ca[3] = {0, 0, 0}, cb[3] = {0, 0, 0};
    for (int m = t; m < MSZ; m += 256) {
        float w = g_rowS[b * MSZ + m] * inv;
        #pragma unroll
        for (int d = 0; d < 3; d++) {
            ca[d] += w * src[((size_t)b * 3 + d) * MSZ + m];
            cb[d] += w * g_wref[(b * MSZ + m) * 3 + d];
        }
    }
    float CA[3], CB[3];
    #pragma unroll
    for (int d = 0; d < 3; d++) CA[d] = blockReduceB(ca[d], sred);
    #pragma unroll
    for (int d = 0; d < 3; d++) CB[d] = blockReduceB(cb[d], sred);

    float cv[9] = {0, 0, 0, 0, 0, 0, 0, 0, 0};
    for (int m = t; m < MSZ; m += 256) {
        float w = g_rowS[b * MSZ + m] * inv;
        float ac[3], bc[3];
        #pragma unroll
        for (int d = 0; d < 3; d++) {
            ac[d] = src[((size_t)b * 3 + d) * MSZ + m] - CA[d];
            bc[d] = g_wref[(b * MSZ + m) * 3 + d] - CB[d];
        }
        #pragma unroll
        for (int i = 0; i < 3; i++)
            #pragma unroll
            for (int j = 0; j < 3; j++)
                cv[i * 3 + j] += ac[i] * bc[j] * w;
    }
    #pragma unroll
    for (int k = 0; k < 9; k++) {
        float r = blockReduceB(cv[k], sred);
        if (t == 0) g_cov[b * 9 + k] = r;
    }
    if (t == 0) {
        #pragma unroll
        for (int d = 0; d < 3; d++) { g_ca[b * 3 + d] = CA[d]; g_cb[b * 3 + d] = CB[d]; }
    }
}

// ---------------- 3x3 SVD (fp64 Jacobi) + Kabsch R,t ----------------
__global__ void svd_kernel(float* __restrict__ out) {
    int b = threadIdx.x;
    if (b >= BATCH) return;

    double A[3][3];
    #pragma unroll
    for (int i = 0; i < 3; i++)
        #pragma unroll
        for (int j = 0; j < 3; j++)
            A[i][j] = (double)g_cov[b * 9 + i * 3 + j];

    double S[3][3];
    #pragma unroll
    for (int i = 0; i < 3; i++)
        #pragma unroll
        for (int j = 0; j < 3; j++) {
            double acc = 0.0;
            #pragma unroll
            for (int k = 0; k < 3; k++) acc += A[k][i] * A[k][j];
            S[i][j] = acc;
        }

    double V[3][3] = {{1, 0, 0}, {0, 1, 0}, {0, 0, 1}};
    const int PP[3] = {0, 0, 1};
    const int QQ[3] = {1, 2, 2};
    for (int sweep = 0; sweep < 20; sweep++) {
        for (int r = 0; r < 3; r++) {
            int p = PP[r], q = QQ[r];
            double apq = S[p][q];
            if (apq == 0.0) continue;
            double theta = (S[q][q] - S[p][p]) / (2.0 * apq);
            double tt = copysign(1.0, theta) / (fabs(theta) + sqrt(1.0 + theta * theta));
            double c = 1.0 / sqrt(1.0 + tt * tt);
            double sn = tt * c;
            for (int k = 0; k < 3; k++) {
                double skp = S[k][p], skq = S[k][q];
                S[k][p] = c * skp - sn * skq;
                S[k][q] = sn * skp + c * skq;
            }
            for (int k = 0; k < 3; k++) {
                double spk = S[p][k], sqk = S[q][k];
                S[p][k] = c * spk - sn * sqk;
                S[q][k] = sn * spk + c * sqk;
            }
            for (int k = 0; k < 3; k++) {
                double vkp = V[k][p], vkq = V[k][q];
                V[k][p] = c * vkp - sn * vkq;
                V[k][q] = sn * vkp + c * vkq;
            }
        }
    }

    double ev[3] = {S[0][0], S[1][1], S[2][2]};
    int idx[3] = {0, 1, 2};
    for (int i = 0; i < 2; i++)
        for (int j = i + 1; j < 3; j++)
            if (ev[idx[j]] > ev[idx[i]]) { int tmp = idx[i]; idx[i] = idx[j]; idx[j] = tmp; }

    double Vs[3][3];
    #pragma unroll
    for (int k = 0; k < 3; k++)
        for (int i = 0; i < 3; i++)
            Vs[k][i] = V[k][idx[i]];

    double U[3][3];
    double nrm[3];
    for (int i = 0; i < 3; i++) {
        double u0 = A[0][0] * Vs[0][i] + A[0][1] * Vs[1][i] + A[0][2] * Vs[2][i];
        double u1 = A[1][0] * Vs[0][i] + A[1][1] * Vs[1][i] + A[1][2] * Vs[2][i];
        double u2 = A[2][0] * Vs[0][i] + A[2][1] * Vs[1][i] + A[2][2] * Vs[2][i];
        double nm = sqrt(u0 * u0 + u1 * u1 + u2 * u2);
        nrm[i] = nm;
        double in = (nm > 1e-300) ? 1.0 / nm : 0.0;
        U[0][i] = u0 * in; U[1][i] = u1 * in; U[2][i] = u2 * in;
    }
    if (nrm[2] < 1e-12 * fmax(nrm[0], 1e-300)) {
        U[0][2] = U[1][0] * U[2][1] - U[2][0] * U[1][1];
        U[1][2] = U[2][0] * U[0][1] - U[0][0] * U[2][1];
        U[2][2] = U[0][0] * U[1][1] - U[1][0] * U[0][1];
    }

    double R[3][3];
    for (int i = 0; i < 3; i++)
        for (int j = 0; j < 3; j++)
            R[i][j] = Vs[i][0] * U[j][0] + Vs[i][1] * U[j][1] + Vs[i][2] * U[j][2];

    double det = R[0][0] * (R[1][1] * R[2][2] - R[1][2] * R[2][1])
               - R[0][1] * (R[1][0] * R[2][2] - R[1][2] * R[2][0])
               + R[0][2] * (R[1][0] * R[2][1] - R[1][1] * R[2][0]);
    if (!(det > 0.0)) {
        for (int i = 0; i < 3; i++)
            for (int j = 0; j < 3; j++)
                R[i][j] -= 2.0 * Vs[i][2] * U[j][2];
    }

    double ca[3] = {(double)g_ca[b * 3], (double)g_ca[b * 3 + 1], (double)g_ca[b * 3 + 2]};
    double cb[3] = {(double)g_cb[b * 3], (double)g_cb[b * 3 + 1], (double)g_cb[b * 3 + 2]};
    double tv[3];
    for (int i = 0; i < 3; i++)
        tv[i] = -(R[i][0] * ca[0] + R[i][1] * ca[1] + R[i][2] * ca[2]) + cb[i];

    for (int i = 0; i < 3; i++)
        for (int j = 0; j < 3; j++)
            out[b * 9 + i * 3 + j] = (float)R[i][j];
    for (int i = 0; i < 3; i++)
        out[288 + b * 3 + i] = (float)tv[i];
}

// ---------------- launch ----------------
extern "C" void kernel_launch(void* const* d_in, const int* in_sizes, int n_in,
                              void* d_out, int out_size) {
    const float* src_emb = (const float*)d_in[0];
    const float* tgt_emb = (const float*)d_in[1];
    const float* src     = (const float*)d_in[2];
    const float* tgt     = (const float*)d_in[3];
    const float* lptr    = (const float*)d_in[4];
    const float* rptr    = (const float*)d_in[5];
    float* out = (float*)d_out;
    float* Pout = out + BATCH * 9 + BATCH * 3;

    dim3 ngrid(BATCH * MSZ / 256, 2);
    norms2_kernel<<<ngrid, 256>>>(src_emb, tgt_emb);
    init_uv_kernel<<<(BATCH * MSZ) / 256, 256>>>();

    dim3 ggrid(NSZ / 128, MSZ / 128, BATCH);
    gemm_mma_kernel<<<ggrid, 256>>>(src_emb, tgt_emb, lptr);

    dim3 sgrid(MSZ / 32, BATCH);
    for (int it = 0; it < SINK_ITERS; it++)
        sink_fused_kernel<<<sgrid, 256>>>(lptr, rptr, it);
    sink_vpow_kernel<<<(BATCH * NSZ) / 256, 256>>>(lptr, rptr, (SINK_ITERS - 1) & 1);

    compute_P_kernel<<<BATCH * MSZ / 4, 256>>>(tgt, Pout);
    cov_kernel<<<BATCH, 256>>>(src);
    svd_kernel<<<1, 32>>>(out);
}

// round 16
// speedup vs baseline: 1.1169x; 1.0157x over previous
#include <cuda_runtime.h>
#include <math.h>
#include <stdint.h>

#define BATCH 32
#define DIMD  512
#define MSZ   1024
#define NSZ   1024
#define SINK_ITERS 5
#define MSPLIT 8
#define SROWS 128

// ---------------- device scratch (static: no allocations) ----------------
__device__ float    g_K [(size_t)BATCH * MSZ * NSZ];   // 134 MB fp32 kernel matrix
__device__ uint16_t g_Kh[(size_t)BATCH * MSZ * NSZ];   //  67 MB bf16 shadow (Sinkhorn reads)
__device__ float g_n1[BATCH * MSZ];
__device__ float g_n2[BATCH * NSZ];
__device__ float g_u[BATCH * MSZ];
__device__ float g_v[BATCH * NSZ];
__device__ float g_vpart[2][(size_t)MSPLIT * BATCH * NSZ];  // double-buffered
__device__ float g_rowS[BATCH * MSZ];
__device__ float g_wref[BATCH * MSZ * 3];
__device__ float g_cov[BATCH * 9];
__device__ float g_ca[BATCH * 3];
__device__ float g_cb[BATCH * 3];

// ---------------- PTX helpers ----------------
__device__ __forceinline__ uint32_t f2tf(float x) {
    uint32_t r;
    asm("cvt.rna.tf32.f32 %0, %1;" : "=r"(r) : "f"(x));
    return r;
}
__device__ __forceinline__ uint32_t pack_bf16x2(float lo, float hi) {
    uint32_t r;
    asm("cvt.rn.bf16x2.f32 %0, %1, %2;" : "=r"(r) : "f"(hi), "f"(lo));
    return r;
}
__device__ __forceinline__ float bf_lo(uint32_t u) { return __uint_as_float(u << 16); }
__device__ __forceinline__ float bf_hi(uint32_t u) { return __uint_as_float(u & 0xFFFF0000u); }

__device__ __forceinline__ void mma_tf32(float* c, uint32_t a0, uint32_t a1,
                                         uint32_t a2, uint32_t a3,
                                         uint32_t b0, uint32_t b1) {
    asm volatile(
        "mma.sync.aligned.m16n8k8.row.col.f32.tf32.tf32.f32 "
        "{%0,%1,%2,%3},{%4,%5,%6,%7},{%8,%9},{%0,%1,%2,%3};"
        : "+f"(c[0]), "+f"(c[1]), "+f"(c[2]), "+f"(c[3])
        : "r"(a0), "r"(a1), "r"(a2), "r"(a3), "r"(b0), "r"(b1));
}

// ---------------- generic helpers ----------------
__device__ __forceinline__ float blockReduceB(float v, volatile float* sred) {
    int lane = threadIdx.x & 31;
    int wid = threadIdx.x >> 5;
    #pragma unroll
    for (int o = 16; o > 0; o >>= 1) v += __shfl_down_sync(0xffffffffu, v, o);
    if (lane == 0) sred[wid] = v;
    __syncthreads();
    if (threadIdx.x < 32) {
        int nw = (blockDim.x + 31) >> 5;
        float x = (threadIdx.x < nw) ? sred[threadIdx.x] : 0.0f;
        #pragma unroll
        for (int o = 16; o > 0; o >>= 1) x += __shfl_down_sync(0xffffffffu, x, o);
        if (threadIdx.x == 0) sred[0] = x;
    }
    __syncthreads();
    float r = sred[0];
    __syncthreads();
    return r;
}

// ---------------- fused norms: grid.y selects src/tgt embedding --------------
__global__ void norms2_kernel(const float* __restrict__ E1, const float* __restrict__ E2) {
    int idx = blockIdx.x * blockDim.x + threadIdx.x;
    const float* E = blockIdx.y ? E2 : E1;
    float* out = blockIdx.y ? g_n2 : g_n1;
    int b = idx >> 10;
    int m = idx & 1023;
    const float* p = E + (size_t)b * DIMD * MSZ + m;
    float s = 0.0f;
    #pragma unroll 8
    for (int d = 0; d < DIMD; d++) {
        float x = p[(size_t)d * MSZ];
        s += x * x;
    }
    out[idx] = sqrtf(s);
}

// ---------------- TF32 mma.sync GEMM + exp epilogue (unchanged) --------------
#define KC 16
#define SSTR 136
__global__ void __launch_bounds__(256, 2) gemm_mma_kernel(
        const float* __restrict__ Ae, const float* __restrict__ Be,
        const float* __restrict__ lptr) {
    __shared__ uint32_t sA[2][KC][SSTR];
    __shared__ uint32_t sB[2][KC][SSTR];

    int b = blockIdx.z;
    int m0 = blockIdx.y * 128;
    int n0 = blockIdx.x * 128;
    int tid = threadIdx.x;
    int wid = tid >> 5;
    int lane = tid & 31;
    int g = lane >> 2;
    int tig = lane & 3;
    int warp_m = (wid >> 2) * 64;
    int warp_n = (wid & 3) * 32;

    const float* Ab = Ae + (size_t)b * DIMD * MSZ;
    const float* Bb = Be + (size_t)b * DIMD * NSZ;

    int kr0 = tid >> 5;
    int c40 = tid & 31;
    int kr1 = (tid + 256) >> 5;
    int c41 = c40;

    float acc[4][4][4];
    #pragma unroll
    for (int mi = 0; mi < 4; mi++)
        #pragma unroll
        for (int ni = 0; ni < 4; ni++)
            #pragma unroll
            for (int q = 0; q < 4; q++) acc[mi][ni][q] = 0.0f;

    float4 ra0, ra1, rb0, rb1;

    ra0 = *(const float4*)&Ab[(size_t)kr0 * MSZ + m0 + c40 * 4];
    ra1 = *(const float4*)&Ab[(size_t)kr1 * MSZ + m0 + c41 * 4];
    rb0 = *(const float4*)&Bb[(size_t)kr0 * NSZ + n0 + c40 * 4];
    rb1 = *(const float4*)&Bb[(size_t)kr1 * NSZ + n0 + c41 * 4];
    {
        uint32_t* pa0 = &sA[0][kr0][c40 * 4];
        uint32_t* pa1 = &sA[0][kr1][c41 * 4];
        uint32_t* pb0 = &sB[0][kr0][c40 * 4];
        uint32_t* pb1 = &sB[0][kr1][c41 * 4];
        pa0[0] = f2tf(ra0.x); pa0[1] = f2tf(ra0.y); pa0[2] = f2tf(ra0.z); pa0[3] = f2tf(ra0.w);
        pa1[0] = f2tf(ra1.x); pa1[1] = f2tf(ra1.y); pa1[2] = f2tf(ra1.z); pa1[3] = f2tf(ra1.w);
        pb0[0] = f2tf(rb0.x); pb0[1] = f2tf(rb0.y); pb0[2] = f2tf(rb0.z); pb0[3] = f2tf(rb0.w);
        pb1[0] = f2tf(rb1.x); pb1[1] = f2tf(rb1.y); pb1[2] = f2tf(rb1.z); pb1[3] = f2tf(rb1.w);
    }
    __syncthreads();

    const int NCH = DIMD / KC;
    for (int c = 0; c < NCH; c++) {
        if (c + 1 < NCH) {
            int kb = (c + 1) * KC;
            ra0 = *(const float4*)&Ab[(size_t)(kb + kr0) * MSZ + m0 + c40 * 4];
            ra1 = *(const float4*)&Ab[(size_t)(kb + kr1) * MSZ + m0 + c41 * 4];
            rb0 = *(const float4*)&Bb[(size_t)(kb + kr0) * NSZ + n0 + c40 * 4];
            rb1 = *(const float4*)&Bb[(size_t)(kb + kr1) * NSZ + n0 + c41 * 4];
        }

        int cb = c & 1;
        #pragma unroll
        for (int ks = 0; ks < 2; ks++) {
            int k0 = ks * 8;
            uint32_t bf[4][2];
            #pragma unroll
            for (int ni = 0; ni < 4; ni++) {
                int nn = warp_n + ni * 8 + g;
                bf[ni][0] = sB[cb][k0 + tig][nn];
                bf[ni][1] = sB[cb][k0 + tig + 4][nn];
            }
            #pragma unroll
            for (int mi = 0; mi < 4; mi++) {
                int mm = warp_m + mi * 16 + g;
                uint32_t a0 = sA[cb][k0 + tig][mm];
                uint32_t a1 = sA[cb][k0 + tig][mm + 8];
                uint32_t a2 = sA[cb][k0 + tig + 4][mm];
                uint32_t a3 = sA[cb][k0 + tig + 4][mm + 8];
                #pragma unroll
                for (int ni = 0; ni < 4; ni++)
                    mma_tf32(acc[mi][ni], a0, a1, a2, a3, bf[ni][0], bf[ni][1]);
            }
        }

        if (c + 1 < NCH) {
            int nb = (c + 1) & 1;
            uint32_t* pa0 = &sA[nb][kr0][c40 * 4];
            uint32_t* pa1 = &sA[nb][kr1][c41 * 4];
            uint32_t* pb0 = &sB[nb][kr0][c40 * 4];
            uint32_t* pb1 = &sB[nb][kr1][c41 * 4];
            pa0[0] = f2tf(ra0.x); pa0[1] = f2tf(ra0.y); pa0[2] = f2tf(ra0.z); pa0[3] = f2tf(ra0.w);
            pa1[0] = f2tf(ra1.x); pa1[1] = f2tf(ra1.y); pa1[2] = f2tf(ra1.z); pa1[3] = f2tf(ra1.w);
            pb0[0] = f2tf(rb0.x); pb0[1] = f2tf(rb0.y); pb0[2] = f2tf(rb0.z); pb0[3] = f2tf(rb0.w);
            pb1[0] = f2tf(rb1.x); pb1[1] = f2tf(rb1.y); pb1[2] = f2tf(rb1.z); pb1[3] = f2tf(rb1.w);
        }
        __syncthreads();
    }

    float linv = 1.0f / fmaxf(lptr[0], 1e-8f);
    float n2r[8];
    #pragma unroll
    for (int ni = 0; ni < 4; ni++) {
        int nc = n0 + warp_n + ni * 8 + 2 * tig;
        n2r[ni * 2]     = g_n2[b * NSZ + nc];
        n2r[ni * 2 + 1] = g_n2[b * NSZ + nc + 1];
    }
    #pragma unroll
    for (int mi = 0; mi < 4; mi++) {
        #pragma unroll
        for (int half = 0; half < 2; half++) {
            int m = m0 + warp_m + mi * 16 + g + half * 8;
            float n1v = g_n1[b * MSZ + m];
            size_t rowoff = ((size_t)(b * MSZ + m)) * NSZ + n0 + warp_n;
            float* Krow = g_K + rowoff;
            uint32_t* Khrow = (uint32_t*)(g_Kh + rowoff);
            #pragma unroll
            for (int ni = 0; ni < 4; ni++) {
                float x0 = acc[mi][ni][half * 2 + 0];
                float x1 = acc[mi][ni][half * 2 + 1];
                float d0 = fmaxf(n1v * n2r[ni * 2], 1e-6f);
                float d1 = fmaxf(n1v * n2r[ni * 2 + 1], 1e-6f);
                float o0 = expf(-(1.0f - x0 / d0) * linv);
                float o1 = expf(-(1.0f - x1 / d1) * linv);
                *(float2*)&Krow[ni * 8 + 2 * tig] = make_float2(o0, o1);
                Khrow[ni * 4 + tig] = pack_bf16x2(o0, o1);
            }
        }
    }
}

// ---------------- fused Sinkhorn: 128 rows/block, amortized phase 0 ----------
// Phase 0: v from previous vpart (MSPLIT=8 partials). Phase A: pipelined row
// sums -> u (warp: 16 rows as 4 pipelined 4-row groups, bit-identical order).
// Phase B: column partials over 128 rows (L2 hits).
__global__ void __launch_bounds__(256) sink_fused_kernel(
        const float* __restrict__ lptr, const float* __restrict__ rptr, int it) {
    __shared__ float sv[1024];
    __shared__ float su[SROWS];
    int b = blockIdx.y;
    int m0 = blockIdx.x * SROWS;
    int tid = threadIdx.x;
    int wid = tid >> 5;
    int lane = tid & 31;

    float lv = lptr[0], rv = rptr[0];
    float fi = rv / fmaxf(rv + lv, 1e-8f);
    float a = 1.0f / (float)MSZ;
    float bb = 1.0f / (float)NSZ;

    // Phase 0: materialize v for this iteration
    if (it == 0) {
        ((float4*)sv)[tid] = make_float4(bb, bb, bb, bb);
    } else {
        const float* vp = g_vpart[(it - 1) & 1];
        float4 s4 = make_float4(0.f, 0.f, 0.f, 0.f);
        #pragma unroll
        for (int z = 0; z < MSPLIT; z++) {
            float4 p4 = *(const float4*)&vp[((size_t)z * BATCH + b) * NSZ + tid * 4];
            s4.x += p4.x; s4.y += p4.y; s4.z += p4.z; s4.w += p4.w;
        }
        float4 v4;
        v4.x = powf(bb / fmaxf(s4.x, 1e-8f), fi);
        v4.y = powf(bb / fmaxf(s4.y, 1e-8f), fi);
        v4.z = powf(bb / fmaxf(s4.z, 1e-8f), fi);
        v4.w = powf(bb / fmaxf(s4.w, 1e-8f), fi);
        ((float4*)sv)[tid] = v4;
    }
    __syncthreads();

    const float4* sv4 = (const float4*)sv;

    // Phase A: warp handles 16 rows (4 pipelined groups of 4)
    #pragma unroll
    for (int grp = 0; grp < 4; grp++) {
        int rbase = b * MSZ + m0 + (wid << 4) + (grp << 2);
        float s[4];
        uint4 buf[2][4];
        {
            const uint4* K0 = (const uint4*)(g_Kh + (size_t)(rbase + 0) * NSZ);
            const uint4* K1 = (const uint4*)(g_Kh + (size_t)(rbase + 1) * NSZ);
            #pragma unroll
            for (int j = 0; j < 4; j++) buf[0][j] = K0[j * 32 + lane];
            #pragma unroll
            for (int j = 0; j < 4; j++) buf[1][j] = K1[j * 32 + lane];
        }
        #pragma unroll
        for (int rr = 0; rr < 4; rr++) {
            uint4 kk[4];
            #pragma unroll
            for (int j = 0; j < 4; j++) kk[j] = buf[rr & 1][j];
            if (rr < 2) {
                const uint4* Kn = (const uint4*)(g_Kh + (size_t)(rbase + rr + 2) * NSZ);
                #pragma unroll
                for (int j = 0; j < 4; j++) buf[rr & 1][j] = Kn[j * 32 + lane];
            }
            float acc = 0.0f;
            #pragma unroll
            for (int j = 0; j < 4; j++) {
                int sl = j * 32 + lane;
                float4 va = sv4[sl * 2];
                float4 vb = sv4[sl * 2 + 1];
                acc += bf_lo(kk[j].x) * va.x + bf_hi(kk[j].x) * va.y
                     + bf_lo(kk[j].y) * va.z + bf_hi(kk[j].y) * va.w
                     + bf_lo(kk[j].z) * vb.x + bf_hi(kk[j].z) * vb.y
                     + bf_lo(kk[j].w) * vb.z + bf_hi(kk[j].w) * vb.w;
            }
            s[rr] = acc;
        }
        #pragma unroll
        for (int o = 16; o > 0; o >>= 1) {
            #pragma unroll
            for (int rr = 0; rr < 4; rr++)
                s[rr] += __shfl_down_sync(0xffffffffu, s[rr], o);
        }
        if (lane == 0) {
            #pragma unroll
            for (int rr = 0; rr < 4; rr++) {
                float uu = powf(a / fmaxf(s[rr], 1e-8f), fi);
                g_u[rbase + rr] = uu;
                su[(wid << 4) + (grp << 2) + rr] = uu;
            }
        }
    }
    __syncthreads();

    // Phase B: column partials over 128 rows (L2 hits)
    const uint16_t* Kbh = g_Kh + (size_t)(b * MSZ + m0) * NSZ;
    float4 acc = make_float4(0.f, 0.f, 0.f, 0.f);
    #pragma unroll 8
    for (int r = 0; r < SROWS; r++) {
        float uu = su[r];
        uint2 kk = *(const uint2*)&Kbh[(size_t)r * NSZ + tid * 4];
        acc.x += uu * bf_lo(kk.x);
        acc.y += uu * bf_hi(kk.x);
        acc.z += uu * bf_lo(kk.y);
        acc.w += uu * bf_hi(kk.y);
    }
    *(float4*)&g_vpart[it & 1][((size_t)blockIdx.x * BATCH + b) * NSZ + tid * 4] = acc;
}

// ---------------- final v materialization ----------------
__global__ void sink_vpow_kernel(const float* __restrict__ lptr,
                                 const float* __restrict__ rptr, int srcbuf) {
    int idx = blockIdx.x * blockDim.x + threadIdx.x;
    int b = idx >> 10;
    int n = idx & 1023;
    const float* vp = g_vpart[srcbuf];
    float s = 0.0f;
    #pragma unroll
    for (int z = 0; z < MSPLIT; z++)
        s += vp[((size_t)z * BATCH + b) * NSZ + n];
    float lv = lptr[0], rv = rptr[0];
    float fi = rv / fmaxf(rv + lv, 1e-8f);
    float bb = 1.0f / (float)NSZ;
    g_v[idx] = powf(bb / fmaxf(s, 1e-8f), fi);
}

// ---------------- P = u*K*v (MLP-4: 4 rows/block, 64 lanes/row) --------------
__global__ void __launch_bounds__(256) compute_P_kernel(
        const float* __restrict__ tgt, float* __restrict__ Pout) {
    __shared__ float sred[8][4];
    int blk = blockIdx.x;
    int tid = threadIdx.x;
    int wpair = tid >> 6;
    int lp = tid & 63;
    int wid = tid >> 5;
    int lane = tid & 31;
    int bm = blk * 4 + wpair;
    int b = bm >> 10;

    float uu = g_u[bm];
    const float4* Krow = (const float4*)(g_K + (size_t)bm * NSZ);
    const float4* vrow = (const float4*)(g_v + b * NSZ);
    float4* Prow = (float4*)(Pout + (size_t)bm * NSZ);
    const float4* t0 = (const float4*)(tgt + ((size_t)b * 3 + 0) * NSZ);
    const float4* t1 = (const float4*)(tgt + ((size_t)b * 3 + 1) * NSZ);
    const float4* t2 = (const float4*)(tgt + ((size_t)b * 3 + 2) * NSZ);

    float rs = 0.f, w0 = 0.f, w1 = 0.f, w2 = 0.f;
    float4 kk[4];
    #pragma unroll
    for (int q = 0; q < 4; q++) kk[q] = Krow[lp + 64 * q];
    #pragma unroll
    for (int q = 0; q < 4; q++) {
        int sl = lp + 64 * q;
        float4 vv = vrow[sl];
        float4 p;
        p.x = uu * kk[q].x * vv.x;
        p.y = uu * kk[q].y * vv.y;
        p.z = uu * kk[q].z * vv.z;
        p.w = uu * kk[q].w * vv.w;
        Prow[sl] = p;
        float4 a0 = t0[sl], a1 = t1[sl], a2 = t2[sl];
        rs += p.x + p.y + p.z + p.w;
        w0 += p.x * a0.x + p.y * a0.y + p.z * a0.z + p.w * a0.w;
        w1 += p.x * a1.x + p.y * a1.y + p.z * a1.z + p.w * a1.w;
        w2 += p.x * a2.x + p.y * a2.y + p.z * a2.z + p.w * a2.w;
    }
    #pragma unroll
    for (int o = 16; o > 0; o >>= 1) {
        rs += __shfl_down_sync(0xffffffffu, rs, o);
        w0 += __shfl_down_sync(0xffffffffu, w0, o);
        w1 += __shfl_down_sync(0xffffffffu, w1, o);
        w2 += __shfl_down_sync(0xffffffffu, w2, o);
    }
    if (lane == 0) {
        sred[wid][0] = rs; sred[wid][1] = w0; sred[wid][2] = w1; sred[wid][3] = w2;
    }
    __syncthreads();
    if (lp == 0) {
        int wa = 2 * wpair, wb = 2 * wpair + 1;
        float RS = sred[wa][0] + sred[wb][0];
        float W0 = sred[wa][1] + sred[wb][1];
        float W1 = sred[wa][2] + sred[wb][2];
        float W2 = sred[wa][3] + sred[wb][3];
        g_rowS[bm] = RS;
        float inv = 1.0f / (RS + 1e-6f);
        g_wref[bm * 3 + 0] = W0 * inv;
        g_wref[bm * 3 + 1] = W1 * inv;
        g_wref[bm * 3 + 2] = W2 * inv;
    }
}

// ---------------- per-batch centroids + covariance ----------------
__global__ void cov_kernel(const float* __restrict__ src) {
    __shared__ float sred[32];
    int b = blockIdx.x;
    int t = threadIdx.x;

    float s = 0.0f;
    for (int m = t; m < MSZ; m += 256) s += g_rowS[b * MSZ + m];
    float S = blockReduceB(s, sred);
    float inv = 1.0f / (S + 1e-6f);

    float ca[3] = {0, 0, 0}, cb[3] = {0, 0, 0};
    for (int m = t; m < MSZ; m += 256) {
        float w = g_rowS[b * MSZ + m] * inv;
        #pragma unroll
        for (int d = 0; d < 3; d++) {
            ca[d] += w * src[((size_t)b * 3 + d) * MSZ + m];
            cb[d] += w * g_wref[(b * MSZ + m) * 3 + d];
        }
    }
    float CA[3], CB[3];
    #pragma unroll
    for (int d = 0; d < 3; d++) CA[d] = blockReduceB(ca[d], sred);
    #pragma unroll
    for (int d = 0; d < 3; d++) CB[d] = blockReduceB(cb[d], sred);

    float cv[9] = {0, 0, 0, 0, 0, 0, 0, 0, 0};
    for (int m = t; m < MSZ; m += 256) {
        float w = g_rowS[b * MSZ + m] * inv;
        float ac[3], bc[3];
        #pragma unroll
        for (int d = 0; d < 3; d++) {
            ac[d] = src[((size_t)b * 3 + d) * MSZ + m] - CA[d];
            bc[d] = g_wref[(b * MSZ + m) * 3 + d] - CB[d];
        }
        #pragma unroll
        for (int i = 0; i < 3; i++)
            #pragma unroll
            for (int j = 0; j < 3; j++)
                cv[i * 3 + j] += ac[i] * bc[j] * w;
    }
    #pragma unroll
    for (int k = 0; k < 9; k++) {
        float r = blockReduceB(cv[k], sred);
        if (t == 0) g_cov[b * 9 + k] = r;
    }
    if (t == 0) {
        #pragma unroll
        for (int d = 0; d < 3; d++) { g_ca[b * 3 + d] = CA[d]; g_cb[b * 3 + d] = CB[d]; }
    }
}

// ---------------- 3x3 SVD (fp64 Jacobi) + Kabsch R,t ----------------
__global__ void svd_kernel(float* __restrict__ out) {
    int b = threadIdx.x;
    if (b >= BATCH) return;

    double A[3][3];
    #pragma unroll
    for (int i = 0; i < 3; i++)
        #pragma unroll
        for (int j = 0; j < 3; j++)
            A[i][j] = (double)g_cov[b * 9 + i * 3 + j];

    double S[3][3];
    #pragma unroll
    for (int i = 0; i < 3; i++)
        #pragma unroll
        for (int j = 0; j < 3; j++) {
            double acc = 0.0;
            #pragma unroll
            for (int k = 0; k < 3; k++) acc += A[k][i] * A[k][j];
            S[i][j] = acc;
        }

    double V[3][3] = {{1, 0, 0}, {0, 1, 0}, {0, 0, 1}};
    const int PP[3] = {0, 0, 1};
    const int QQ[3] = {1, 2, 2};
    for (int sweep = 0; sweep < 20; sweep++) {
        for (int r = 0; r < 3; r++) {
            int p = PP[r], q = QQ[r];
            double apq = S[p][q];
            if (apq == 0.0) continue;
            double theta = (S[q][q] - S[p][p]) / (2.0 * apq);
            double tt = copysign(1.0, theta) / (fabs(theta) + sqrt(1.0 + theta * theta));
            double c = 1.0 / sqrt(1.0 + tt * tt);
            double sn = tt * c;
            for (int k = 0; k < 3; k++) {
                double skp = S[k][p], skq = S[k][q];
                S[k][p] = c * skp - sn * skq;
                S[k][q] = sn * skp + c * skq;
            }
            for (int k = 0; k < 3; k++) {
                double spk = S[p][k], sqk = S[q][k];
                S[p][k] = c * spk - sn * sqk;
                S[q][k] = sn * spk + c * sqk;
            }
            for (int k = 0; k < 3; k++) {
                double vkp = V[k][p], vkq = V[k][q];
                V[k][p] = c * vkp - sn * vkq;
                V[k][q] = sn * vkp + c * vkq;
            }
        }
    }

    double ev[3] = {S[0][0], S[1][1], S[2][2]};
    int idx[3] = {0, 1, 2};
    for (int i = 0; i < 2; i++)
        for (int j = i + 1; j < 3; j++)
            if (ev[idx[j]] > ev[idx[i]]) { int tmp = idx[i]; idx[i] = idx[j]; idx[j] = tmp; }

    double Vs[3][3];
    #pragma unroll
    for (int k = 0; k < 3; k++)
        for (int i = 0; i < 3; i++)
            Vs[k][i] = V[k][idx[i]];

    double U[3][3];
    double nrm[3];
    for (int i = 0; i < 3; i++) {
        double u0 = A[0][0] * Vs[0][i] + A[0][1] * Vs[1][i] + A[0][2] * Vs[2][i];
        double u1 = A[1][0] * Vs[0][i] + A[1][1] * Vs[1][i] + A[1][2] * Vs[2][i];
        double u2 = A[2][0] * Vs[0][i] + A[2][1] * Vs[1][i] + A[2][2] * Vs[2][i];
        double nm = sqrt(u0 * u0 + u1 * u1 + u2 * u2);
        nrm[i] = nm;
        double in = (nm > 1e-300) ? 1.0 / nm : 0.0;
        U[0][i] = u0 * in; U[1][i] = u1 * in; U[2][i] = u2 * in;
    }
    if (nrm[2] < 1e-12 * fmax(nrm[0], 1e-300)) {
        U[0][2] = U[1][0] * U[2][1] - U[2][0] * U[1][1];
        U[1][2] = U[2][0] * U[0][1] - U[0][0] * U[2][1];
        U[2][2] = U[0][0] * U[1][1] - U[1][0] * U[0][1];
    }

    double R[3][3];
    for (int i = 0; i < 3; i++)
        for (int j = 0; j < 3; j++)
            R[i][j] = Vs[i][0] * U[j][0] + Vs[i][1] * U[j][1] + Vs[i][2] * U[j][2];

    double det = R[0][0] * (R[1][1] * R[2][2] - R[1][2] * R[2][1])
               - R[0][1] * (R[1][0] * R[2][2] - R[1][2] * R[2][0])
               + R[0][2] * (R[1][0] * R[2][1] - R[1][1] * R[2][0]);
    if (!(det > 0.0)) {
        for (int i = 0; i < 3; i++)
            for (int j = 0; j < 3; j++)
                R[i][j] -= 2.0 * Vs[i][2] * U[j][2];
    }

    double ca[3] = {(double)g_ca[b * 3], (double)g_ca[b * 3 + 1], (double)g_ca[b * 3 + 2]};
    double cb[3] = {(double)g_cb[b * 3], (double)g_cb[b * 3 + 1], (double)g_cb[b * 3 + 2]};
    double tv[3];
    for (int i = 0; i < 3; i++)
        tv[i] = -(R[i][0] * ca[0] + R[i][1] * ca[1] + R[i][2] * ca[2]) + cb[i];

    for (int i = 0; i < 3; i++)
        for (int j = 0; j < 3; j++)
            out[b * 9 + i * 3 + j] = (float)R[i][j];
    for (int i = 0; i < 3; i++)
        out[288 + b * 3 + i] = (float)tv[i];
}

// ---------------- launch ----------------
extern "C" void kernel_launch(void* const* d_in, const int* in_sizes, int n_in,
                              void* d_out, int out_size) {
    const float* src_emb = (const float*)d_in[0];
    const float* tgt_emb = (const float*)d_in[1];
    const float* src     = (const float*)d_in[2];
    const float* tgt     = (const float*)d_in[3];
    const float* lptr    = (const float*)d_in[4];
    const float* rptr    = (const float*)d_in[5];
    float* out = (float*)d_out;
    float* Pout = out + BATCH * 9 + BATCH * 3;

    dim3 ngrid(BATCH * MSZ / 256, 2);
    norms2_kernel<<<ngrid, 256>>>(src_emb, tgt_emb);

    dim3 ggrid(NSZ / 128, MSZ / 128, BATCH);
    gemm_mma_kernel<<<ggrid, 256>>>(src_emb, tgt_emb, lptr);

    dim3 sgrid(MSZ / SROWS, BATCH);
    for (int it = 0; it < SINK_ITERS; it++)
        sink_fused_kernel<<<sgrid, 256>>>(lptr, rptr, it);
    sink_vpow_kernel<<<(BATCH * NSZ) / 256, 256>>>(lptr, rptr, (SINK_ITERS - 1) & 1);

    compute_P_kernel<<<BATCH * MSZ / 4, 256>>>(tgt, Pout);
    cov_kernel<<<BATCH, 256>>>(src);
    svd_kernel<<<1, 32>>>(out);
}